// round 2
// baseline (speedup 1.0000x reference)
#include <cuda_runtime.h>
#include <cuda_bf16.h>
#include <math.h>
#include <mma.h>

using namespace nvcuda;

// Problem dims
#define B_   64
#define DV_  2048
#define WH_  196
#define DQ_  2400
#define DA_  1200
#define G_   2
#define DH_  1200
#define NC_  3000
#define MROWS (B_*WH_)   // 12544

// ---------------- scratch (device globals; no allocation allowed) ----------
__device__ float g_xatt[MROWS * DA_];        // [B*196, 1200]  ~60 MB
__device__ float g_xq  [B_ * DA_];           // [64, 1200]
__device__ float g_att [B_ * G_ * WH_];      // [64, 2, 196]
__device__ float g_vatt[B_ * G_ * DV_];      // [64, 2, 2048]
__device__ float g_vfus[B_ * G_ * DH_];      // [64, 2400]
__device__ float g_qfus[B_ * G_ * DH_];      // [64, 2400]

// ---------------------------------------------------------------------------
// GEMM1 on tensor cores: 3xTF32 wmma (hi*hi + hi*lo + lo*hi ~= fp32 accuracy).
// C[m,n] = tanh( tanh( sum_k V[b,k,ns]*W[n,k] + bias[n] ) * xq[b,n] ),
// m=(b,ns), M=12544, N=1200, K=2048.
// Block tile 128x128x32, 8 warps, warp tile 32x64 (2x4 wmma 16x16 frags).
// ---------------------------------------------------------------------------
#define BM 128
#define BN 128
#define BK 32

__global__ __launch_bounds__(256, 1)
void gemm_tf32_att(const float* __restrict__ V,     // input_v [64,2048,196]
                   const float* __restrict__ W,     // Wv_att  [1200,2048]
                   const float* __restrict__ bias,  // [1200]
                   const float* __restrict__ xq,    // [64,1200]
                   float* __restrict__ C)           // xatt [12544,1200]
{
    __shared__ float As[BK][136];    // A col-major: As[k][m], pad 136
    __shared__ float Bs[BN][40];     // Bs[n][k], pad 40
    __shared__ float stage[8][256];  // per-warp 16x16 epilogue staging

    const int tid  = threadIdx.x;
    const int warp = tid >> 5;
    const int lane = tid & 31;
    const int m0 = blockIdx.y * BM;
    const int n0 = blockIdx.x * BN;
    const int wm = (warp & 3) * 32;   // warp row offset in tile
    const int wn = (warp >> 2) * 64;  // warp col offset in tile

    // --- A load mapping: m = tid&127 (fixed), k = 2*i + (tid>>7) ---
    const int m_local = tid & 127;
    const int k_off_a = tid >> 7;            // 0 or 1
    {
        // precompute nothing heavy; b/ns fixed per thread
    }
    const int mg    = m0 + m_local;
    const int bidx  = mg / WH_;
    const int ns    = mg - bidx * WH_;
    const long abase = (long)bidx * DV_ * WH_ + ns;

    // --- B load mapping: k = tid&31 (fixed), n = i*8 + (tid>>5) ---
    const int kb = tid & 31;
    const int nb = tid >> 5;                 // 0..7

    wmma::fragment<wmma::accumulator, 16, 16, 8, float> c[2][4];
#pragma unroll
    for (int mi = 0; mi < 2; mi++)
#pragma unroll
        for (int ni = 0; ni < 4; ni++) wmma::fill_fragment(c[mi][ni], 0.0f);

    for (int k0 = 0; k0 < DV_; k0 += BK) {
        // stage A tile (conflict-free smem stores, coalesced gmem over ns)
#pragma unroll
        for (int i = 0; i < 16; i++) {
            int k = 2 * i + k_off_a;
            As[k][m_local] = V[abase + (long)(k0 + k) * WH_];
        }
        // stage B tile
#pragma unroll
        for (int i = 0; i < 16; i++) {
            int n_local = i * 8 + nb;
            int ng = n0 + n_local;
            Bs[n_local][kb] = (ng < DA_) ? W[(long)ng * DV_ + k0 + kb] : 0.f;
        }
        __syncthreads();

#pragma unroll
        for (int ks = 0; ks < BK / 8; ks++) {
            wmma::fragment<wmma::matrix_a, 16, 16, 8, wmma::precision::tf32, wmma::col_major> a_hi[2], a_lo[2];
            wmma::fragment<wmma::matrix_b, 16, 16, 8, wmma::precision::tf32, wmma::col_major> b_hi[4], b_lo[4];
#pragma unroll
            for (int mi = 0; mi < 2; mi++) {
                wmma::fragment<wmma::matrix_a, 16, 16, 8, wmma::precision::tf32, wmma::col_major> ar;
                wmma::load_matrix_sync(ar, &As[ks * 8][wm + mi * 16], 136);
#pragma unroll
                for (int e = 0; e < ar.num_elements; e++) {
                    float x = ar.x[e];
                    float h = wmma::__float_to_tf32(x);
                    a_hi[mi].x[e] = h;
                    a_lo[mi].x[e] = wmma::__float_to_tf32(x - h);
                }
            }
#pragma unroll
            for (int ni = 0; ni < 4; ni++) {
                wmma::fragment<wmma::matrix_b, 16, 16, 8, wmma::precision::tf32, wmma::col_major> br;
                wmma::load_matrix_sync(br, &Bs[wn + ni * 16][ks * 8], 40);
#pragma unroll
                for (int e = 0; e < br.num_elements; e++) {
                    float x = br.x[e];
                    float h = wmma::__float_to_tf32(x);
                    b_hi[ni].x[e] = h;
                    b_lo[ni].x[e] = wmma::__float_to_tf32(x - h);
                }
            }
#pragma unroll
            for (int mi = 0; mi < 2; mi++)
#pragma unroll
                for (int ni = 0; ni < 4; ni++) {
                    wmma::mma_sync(c[mi][ni], a_hi[mi], b_hi[ni], c[mi][ni]);
                    wmma::mma_sync(c[mi][ni], a_hi[mi], b_lo[ni], c[mi][ni]);
                    wmma::mma_sync(c[mi][ni], a_lo[mi], b_hi[ni], c[mi][ni]);
                }
        }
        __syncthreads();
    }

    // --- fused epilogue: tanh(tanh(acc+bias)*xq) ---
    const int r  = lane >> 1;          // 0..15
    const int c0 = (lane & 1) * 8;     // 0 or 8
#pragma unroll
    for (int mi = 0; mi < 2; mi++) {
#pragma unroll
        for (int ni = 0; ni < 4; ni++) {
            int nbase = n0 + wn + ni * 16;
            wmma::store_matrix_sync(&stage[warp][0], c[mi][ni], 16, wmma::mem_row_major);
            __syncwarp();
            if (nbase < DA_) {   // DA_=1200 is 16-aligned: frag fully valid or fully out
                int mrow = m0 + wm + mi * 16 + r;
                int bb   = mrow / WH_;
                const float* xqr = xq + (long)bb * DA_;
                float* crow = C + (long)mrow * DA_;
#pragma unroll
                for (int j = 0; j < 8; j++) {
                    int n = nbase + c0 + j;
                    float v = stage[warp][r * 16 + c0 + j] + bias[n];
                    float t1 = tanhf(v);
                    crow[n] = tanhf(t1 * xqr[n]);
                }
            }
            __syncwarp();
        }
    }
}

// ---------------------------------------------------------------------------
// Small tiled GEMM: 64x64 tile, BK=16, 256 threads, 4x4 per thread.
// Batched over blockIdx.z via element strides (for the 2 glimpses).
// MODE 1: C = tanh(acc + bias[n]);  MODE 2: A[m,k]=A*extra elementwise, C=acc+bias
// ---------------------------------------------------------------------------
template<int MODE>
__global__ void gemm64(const float* __restrict__ A,
                       const float* __restrict__ W,
                       const float* __restrict__ bias,
                       const float* __restrict__ extra,
                       float* __restrict__ C,
                       int M, int N, int K, int lda, int ldc,
                       long aBS, long wBS, long bBS, long cBS)
{
    const int g = blockIdx.z;
    A    += (long)g * aBS;
    W    += (long)g * wBS;
    bias += (long)g * bBS;
    C    += (long)g * cBS;

    __shared__ float As[16][64];
    __shared__ float Bs[16][64];

    const int tid = threadIdx.x;
    const int ty  = tid >> 4;      // 0..15
    const int tx  = tid & 15;      // 0..15
    const int m0  = blockIdx.y * 64;
    const int n0  = blockIdx.x * 64;

    float acc[4][4];
#pragma unroll
    for (int i = 0; i < 4; i++)
#pragma unroll
        for (int j = 0; j < 4; j++) acc[i][j] = 0.f;

    for (int k0 = 0; k0 < K; k0 += 16) {
#pragma unroll
        for (int i = 0; i < 4; i++) {
            int e = i * 256 + tid;
            int m = e & 63, k = e >> 6;
            int mg = m0 + m;
            float v = 0.f;
            if (mg < M) {
                long idx = (long)mg * lda + k0 + k;
                v = A[idx];
                if (MODE == 2) v *= extra[idx];
            }
            As[k][m] = v;
        }
#pragma unroll
        for (int i = 0; i < 4; i++) {
            int e = i * 256 + tid;
            int k = e & 15, n = e >> 4;
            int ng = n0 + n;
            Bs[k][n] = (ng < N) ? W[(long)ng * K + k0 + k] : 0.f;
        }
        __syncthreads();

#pragma unroll
        for (int kk = 0; kk < 16; kk++) {
            float a[4], b[4];
#pragma unroll
            for (int i = 0; i < 4; i++) a[i] = As[kk][ty * 4 + i];
#pragma unroll
            for (int j = 0; j < 4; j++) b[j] = Bs[kk][tx * 4 + j];
#pragma unroll
            for (int i = 0; i < 4; i++)
#pragma unroll
                for (int j = 0; j < 4; j++) acc[i][j] += a[i] * b[j];
        }
        __syncthreads();
    }

#pragma unroll
    for (int i = 0; i < 4; i++) {
        int mg = m0 + ty * 4 + i;
        if (mg >= M) continue;
#pragma unroll
        for (int j = 0; j < 4; j++) {
            int n = n0 + tx * 4 + j;
            if (n >= N) continue;
            float v = acc[i][j] + bias[n];
            C[(long)mg * ldc + n] = (MODE == 1) ? tanhf(v) : v;
        }
    }
}

// ---------------------------------------------------------------------------
// wgt[b,g,n] = sum_d xatt[b,n,d] * Watt[g,d] + batt[g]   (one warp per (b,n))
// ---------------------------------------------------------------------------
__global__ void wgt_kernel(const float* __restrict__ xatt,
                           const float* __restrict__ Watt,
                           const float* __restrict__ batt,
                           float* __restrict__ out)
{
    int w    = (blockIdx.x * blockDim.x + threadIdx.x) >> 5;
    int lane = threadIdx.x & 31;
    if (w >= MROWS) return;
    int b = w / WH_, n = w - b * WH_;
    const float* xr = xatt + (long)w * DA_;
    float s0 = 0.f, s1 = 0.f;
    for (int d = lane; d < DA_; d += 32) {
        float x = xr[d];
        s0 += x * Watt[d];
        s1 += x * Watt[DA_ + d];
    }
#pragma unroll
    for (int o = 16; o > 0; o >>= 1) {
        s0 += __shfl_down_sync(0xffffffffu, s0, o);
        s1 += __shfl_down_sync(0xffffffffu, s1, o);
    }
    if (lane == 0) {
        out[((long)b * G_ + 0) * WH_ + n] = s0 + batt[0];
        out[((long)b * G_ + 1) * WH_ + n] = s1 + batt[1];
    }
}

// softmax over 196 per (b,g)
__global__ void softmax196(const float* __restrict__ wgt, float* __restrict__ att)
{
    __shared__ float red[256];
    int bg = blockIdx.x;          // 0..127
    int t  = threadIdx.x;         // 0..255
    const float* in = wgt + (long)bg * WH_;
    float v = (t < WH_) ? in[t] : -1e30f;
    red[t] = v; __syncthreads();
    for (int s = 128; s > 0; s >>= 1) {
        if (t < s) red[t] = fmaxf(red[t], red[t + s]);
        __syncthreads();
    }
    float mx = red[0]; __syncthreads();
    float e = (t < WH_) ? expf(v - mx) : 0.f;
    red[t] = e; __syncthreads();
    for (int s = 128; s > 0; s >>= 1) {
        if (t < s) red[t] += red[t + s];
        __syncthreads();
    }
    float inv = 1.f / red[0];
    if (t < WH_) att[(long)bg * WH_ + t] = e * inv;
}

// v_att[b,g,d] = sum_n att[b,g,n] * input_v[b,d,n]
__global__ void vatt_kernel(const float* __restrict__ v,
                            const float* __restrict__ att,
                            float* __restrict__ vatt)
{
    __shared__ float a0[WH_], a1[WH_];
    int b = blockIdx.x;
    int t = threadIdx.x;
    if (t < WH_) {
        a0[t] = att[((long)b * G_ + 0) * WH_ + t];
        a1[t] = att[((long)b * G_ + 1) * WH_ + t];
    }
    __syncthreads();
    int lane = t & 31, dd = t >> 5;
    int d = blockIdx.y * 8 + dd;
    const float* row = v + ((long)b * DV_ + d) * WH_;
    float s0 = 0.f, s1 = 0.f;
    for (int n = lane; n < WH_; n += 32) {
        float x = row[n];
        s0 += x * a0[n];
        s1 += x * a1[n];
    }
#pragma unroll
    for (int o = 16; o > 0; o >>= 1) {
        s0 += __shfl_down_sync(0xffffffffu, s0, o);
        s1 += __shfl_down_sync(0xffffffffu, s1, o);
    }
    if (lane == 0) {
        vatt[((long)b * G_ + 0) * DV_ + d] = s0;
        vatt[((long)b * G_ + 1) * DV_ + d] = s1;
    }
}

// ---------------------------------------------------------------------------
extern "C" void kernel_launch(void* const* d_in, const int* in_sizes, int n_in,
                              void* d_out, int out_size)
{
    const float* input_q = (const float*)d_in[0];
    const float* input_v = (const float*)d_in[1];
    const float* Wv_att  = (const float*)d_in[2];
    const float* bv_att  = (const float*)d_in[3];
    const float* Wq_att  = (const float*)d_in[4];
    const float* bq_att  = (const float*)d_in[5];
    const float* Watt    = (const float*)d_in[6];
    const float* batt    = (const float*)d_in[7];
    const float* Wv_fus  = (const float*)d_in[8];
    const float* bv_fus  = (const float*)d_in[9];
    const float* Wq_fus  = (const float*)d_in[10];
    const float* bq_fus  = (const float*)d_in[11];
    const float* Wc      = (const float*)d_in[12];
    const float* bc      = (const float*)d_in[13];

    float* out     = (float*)d_out;
    float* wgt_out = out + B_ * NC_;   // wgt tail of output tuple

    float *xatt, *xq, *att, *vatt, *vfus, *qfus;
    cudaGetSymbolAddress((void**)&xatt, g_xatt);
    cudaGetSymbolAddress((void**)&xq,   g_xq);
    cudaGetSymbolAddress((void**)&att,  g_att);
    cudaGetSymbolAddress((void**)&vatt, g_vatt);
    cudaGetSymbolAddress((void**)&vfus, g_vfus);
    cudaGetSymbolAddress((void**)&qfus, g_qfus);

    // 1) xq = tanh(input_q @ Wq_att^T + bq_att)          [64, 1200]
    gemm64<1><<<dim3((DA_ + 63) / 64, 1, 1), 256>>>(
        input_q, Wq_att, bq_att, nullptr, xq,
        B_, DA_, DQ_, DQ_, DA_, 0, 0, 0, 0);

    // 2) xatt = tanh( tanh(V^T Wv_att^T + b) * xq )      [12544, 1200]  (3xTF32 tensor)
    gemm_tf32_att<<<dim3((DA_ + BN - 1) / BN, MROWS / BM), 256>>>(
        input_v, Wv_att, bv_att, xq, xatt);

    // 3) wgt (also part of output)                       [64, 2, 196]
    wgt_kernel<<<(MROWS * 32 + 255) / 256, 256>>>(xatt, Watt, batt, wgt_out);

    // 4) att = softmax(wgt, axis=n)
    softmax196<<<B_ * G_, 256>>>(wgt_out, att);

    // 5) v_att = att @ V                                 [64, 2, 2048]
    vatt_kernel<<<dim3(B_, DV_ / 8), 256>>>(input_v, att, vatt);

    // 6) v_fus = tanh(v_att @ Wv_fus^T + b)  batched g   -> [64, 2400]
    gemm64<1><<<dim3((DH_ + 63) / 64, 1, G_), 256>>>(
        vatt, Wv_fus, bv_fus, nullptr, vfus,
        B_, DH_, DV_, G_ * DV_, G_ * DH_,
        (long)DV_, (long)DH_ * DV_, (long)DH_, (long)DH_);

    // 7) q_fus = tanh(input_q @ Wq_fus^T + b)            [64, 2400]
    gemm64<1><<<dim3((G_ * DH_ + 63) / 64, 1, 1), 256>>>(
        input_q, Wq_fus, bq_fus, nullptr, qfus,
        B_, G_ * DH_, DQ_, DQ_, G_ * DH_, 0, 0, 0, 0);

    // 8) x = (v_fus * q_fus) @ Wc^T + bc                 [64, 3000]
    gemm64<2><<<dim3((NC_ + 63) / 64, 1, 1), 256>>>(
        vfus, Wc, bc, qfus, out,
        B_, NC_, G_ * DH_, G_ * DH_, NC_, 0, 0, 0, 0);
}

// round 5
// speedup vs baseline: 1.9531x; 1.9531x over previous
#include <cuda_runtime.h>
#include <cuda_bf16.h>
#include <math.h>
#include <cstdint>

// Problem dims
#define B_   64
#define DV_  2048
#define WH_  196
#define DQ_  2400
#define DA_  1200
#define G_   2
#define DH_  1200
#define NC_  3000
#define MROWS (B_*WH_)   // 12544

// ---------------- scratch (device globals; no allocation allowed) ----------
__device__ float g_xatt[MROWS * DA_];        // [12544, 1200]
__device__ float g_xq  [B_ * DA_];
__device__ float g_att [B_ * G_ * WH_];
__device__ float g_vatt[B_ * G_ * DV_];
__device__ float g_vfus[B_ * G_ * DH_];
__device__ float g_qfus[B_ * G_ * DH_];
// bf16 split operands for GEMM1 (A = V transposed to [M,K] K-major)
__device__ __nv_bfloat16 g_Ahi[(size_t)MROWS * DV_];
__device__ __nv_bfloat16 g_Alo[(size_t)MROWS * DV_];
__device__ __nv_bfloat16 g_Bhi[(size_t)DA_ * DV_];
__device__ __nv_bfloat16 g_Blo[(size_t)DA_ * DV_];

// ============================ PTX helpers ==================================
__device__ __forceinline__ uint32_t smem_u32(const void* p) {
    uint32_t a;
    asm("{ .reg .u64 t; cvta.to.shared.u64 t, %1; cvt.u32.u64 %0, t; }" : "=r"(a) : "l"(p));
    return a;
}
__device__ __forceinline__ void cp16(uint32_t dst, const void* src) {
    asm volatile("cp.async.cg.shared.global [%0], [%1], 16;" :: "r"(dst), "l"(src));
}
#define CP_COMMIT() asm volatile("cp.async.commit_group;" ::: "memory")
#define CP_WAIT(n)  asm volatile("cp.async.wait_group %0;" :: "n"(n) : "memory")

__device__ __forceinline__ void ldsm_x4(uint32_t* r, uint32_t addr) {
    asm volatile("ldmatrix.sync.aligned.m8n8.x4.shared.b16 {%0,%1,%2,%3}, [%4];"
                 : "=r"(r[0]), "=r"(r[1]), "=r"(r[2]), "=r"(r[3]) : "r"(addr));
}
__device__ __forceinline__ void mma_bf16(float* c, const uint32_t* a, const uint32_t* b) {
    asm volatile("mma.sync.aligned.m16n8k16.row.col.f32.bf16.bf16.f32 "
                 "{%0,%1,%2,%3}, {%4,%5,%6,%7}, {%8,%9}, {%0,%1,%2,%3};"
                 : "+f"(c[0]), "+f"(c[1]), "+f"(c[2]), "+f"(c[3])
                 : "r"(a[0]), "r"(a[1]), "r"(a[2]), "r"(a[3]), "r"(b[0]), "r"(b[1]));
}

// ============================ prepack kernels ==============================
__device__ __forceinline__ void split_bf16(float x, __nv_bfloat16& hi, __nv_bfloat16& lo) {
    hi = __float2bfloat16(x);
    lo = __float2bfloat16(x - __bfloat162float(hi));
}

// Wv_att [1200, 2048] row-major (K contiguous) -> hi/lo, same layout
__global__ void pack_W(const float* __restrict__ W) {
    size_t i = (size_t)blockIdx.x * blockDim.x + threadIdx.x;
    size_t total = (size_t)DA_ * DV_ / 4;
    if (i >= total) return;
    const float4 v = ((const float4*)W)[i];
    __nv_bfloat16 h0, l0, h1, l1, h2, l2, h3, l3;
    split_bf16(v.x, h0, l0); split_bf16(v.y, h1, l1);
    split_bf16(v.z, h2, l2); split_bf16(v.w, h3, l3);
    __nv_bfloat162* Hi = (__nv_bfloat162*)g_Bhi;
    __nv_bfloat162* Lo = (__nv_bfloat162*)g_Blo;
    Hi[i * 2 + 0] = __nv_bfloat162(h0, h1); Hi[i * 2 + 1] = __nv_bfloat162(h2, h3);
    Lo[i * 2 + 0] = __nv_bfloat162(l0, l1); Lo[i * 2 + 1] = __nv_bfloat162(l2, l3);
}

// input_v [64, 2048, 196] -> A[m=(b,ns)][k] bf16 hi/lo (transpose via smem tile)
__global__ void pack_A(const float* __restrict__ V) {
    __shared__ float tile[32][33];
    int ns0 = blockIdx.x * 32;       // 7 tiles cover 196
    int k0  = blockIdx.y * 32;       // 64 tiles cover 2048
    int b   = blockIdx.z;
    int tx = threadIdx.x, ty = threadIdx.y;   // (32, 8)
#pragma unroll
    for (int r = 0; r < 4; r++) {
        int kl = ty + r * 8;
        int ns = ns0 + tx;
        float v = (ns < WH_) ? V[((size_t)b * DV_ + (k0 + kl)) * WH_ + ns] : 0.f;
        tile[kl][tx] = v;
    }
    __syncthreads();
#pragma unroll
    for (int r = 0; r < 4; r++) {
        int nsl = ty + r * 8;
        int ns = ns0 + nsl;
        if (ns < WH_) {
            size_t m = (size_t)b * WH_ + ns;
            float v = tile[tx][nsl];
            __nv_bfloat16 hi, lo;
            split_bf16(v, hi, lo);
            g_Ahi[m * DV_ + k0 + tx] = hi;
            g_Alo[m * DV_ + k0 + tx] = lo;
        }
    }
}

// ============================ GEMM1 (mma.sync bf16, 3x split) ==============
// C[m,n] = tanh( tanh( sum_k A[m,k]*W[n,k] + bias[n] ) * xq[b,n] )
// M=12544, N=1200, K=2048. Block 128x128x32, 8 warps (2m x 4n), warp 64x32.
// SMEM stage: A hi/lo + B hi/lo, 128 rows x 80B each (row = 32 bf16 + pad).
#define APART  10240           // 128 * 80
#define STG_B  20480
#define STAGE  40960
#define SMEM_G1 (2 * STAGE)    // 81920

__global__ void __launch_bounds__(256, 1)
gemm1_mma(const float* __restrict__ bias, const float* __restrict__ xq,
          float* __restrict__ C)
{
    extern __shared__ char sm[];
    const uint32_t sb = smem_u32(sm);
    const int tid = threadIdx.x, warp = tid >> 5, lane = tid & 31;
    const int m0 = blockIdx.y * 128;
    const int n0 = blockIdx.x * 128;
    const int wm = (warp & 1) * 64;
    const int wn = (warp >> 1) * 32;

    float acc[4][4][4];
#pragma unroll
    for (int mi = 0; mi < 4; mi++)
#pragma unroll
        for (int nf = 0; nf < 4; nf++)
#pragma unroll
            for (int e = 0; e < 4; e++) acc[mi][nf][e] = 0.f;

    // per-thread load coordinates (row = idx>>2, 16B chunk = idx&3)
    const int r_a = tid >> 2, c_a = tid & 3;

    auto load_stage = [&](int ks, int buf) {
        const int k0 = ks * 32;
        const uint32_t dstA = sb + buf * STAGE;
        const uint32_t dstB = dstA + STG_B;
#pragma unroll
        for (int part = 0; part < 2; part++) {
            const __nv_bfloat16* src = part ? g_Alo : g_Ahi;
#pragma unroll
            for (int i = 0; i < 2; i++) {
                int row = r_a + i * 64;
                cp16(dstA + part * APART + row * 80 + c_a * 16,
                     src + (size_t)(m0 + row) * DV_ + k0 + c_a * 8);
            }
        }
#pragma unroll
        for (int part = 0; part < 2; part++) {
            const __nv_bfloat16* src = part ? g_Blo : g_Bhi;
#pragma unroll
            for (int i = 0; i < 2; i++) {
                int row = r_a + i * 64;
                int rg = n0 + row; if (rg >= DA_) rg = DA_ - 1;   // clamp; masked at store
                cp16(dstB + part * APART + row * 80 + c_a * 16,
                     src + (size_t)rg * DV_ + k0 + c_a * 8);
            }
        }
    };

    load_stage(0, 0);
    CP_COMMIT();

    const int NST = DV_ / 32;   // 64
    for (int ks = 0; ks < NST; ks++) {
        const int buf = ks & 1;
        if (ks + 1 < NST) { load_stage(ks + 1, buf ^ 1); CP_COMMIT(); CP_WAIT(1); }
        else              { CP_WAIT(0); }
        __syncthreads();

        const uint32_t Ab = sb + buf * STAGE;
        const uint32_t Bb = Ab + STG_B;
#pragma unroll
        for (int kb2 = 0; kb2 < 2; kb2++) {
            const int kb = kb2 * 16;
            uint32_t a_hi[4][4], a_lo[4][4], b_hi[2][4], b_lo[2][4];
            // A frags: lanes 0-15 -> rows, lanes 16-31 -> +8 cols (16B)
            const uint32_t aAddr = Ab + (wm + (lane & 15)) * 80 + kb * 2 + ((lane >> 4) << 4);
#pragma unroll
            for (int mi = 0; mi < 4; mi++) {
                ldsm_x4(a_hi[mi], aAddr + mi * 16 * 80);
                ldsm_x4(a_lo[mi], aAddr + APART + mi * 16 * 80);
            }
            // B frags: groups (n0-7,k0),(n0-7,k8),(n8-15,k0),(n8-15,k8)
            const uint32_t bAddr = Bb + (wn + ((lane >> 4) << 3) + (lane & 7)) * 80
                                 + (kb + ((lane >> 3) & 1) * 8) * 2;
#pragma unroll
            for (int nj = 0; nj < 2; nj++) {
                ldsm_x4(b_hi[nj], bAddr + nj * 16 * 80);
                ldsm_x4(b_lo[nj], bAddr + APART + nj * 16 * 80);
            }
#pragma unroll
            for (int mi = 0; mi < 4; mi++)
#pragma unroll
                for (int nf = 0; nf < 4; nf++) {
                    const uint32_t* bh = &b_hi[nf >> 1][(nf & 1) * 2];
                    const uint32_t* bl = &b_lo[nf >> 1][(nf & 1) * 2];
                    mma_bf16(acc[mi][nf], a_hi[mi], bh);
                    mma_bf16(acc[mi][nf], a_hi[mi], bl);
                    mma_bf16(acc[mi][nf], a_lo[mi], bh);
                }
        }
        __syncthreads();
    }

    // --- fused epilogue: tanh(tanh(acc+bias)*xq), float2 stores ---
#pragma unroll
    for (int mi = 0; mi < 4; mi++) {
        const int r0 = m0 + wm + mi * 16 + (lane >> 2);
        const int r1 = r0 + 8;
        const int b0 = r0 / WH_, b1 = r1 / WH_;
        const float* xq0 = xq + (size_t)b0 * DA_;
        const float* xq1 = xq + (size_t)b1 * DA_;
#pragma unroll
        for (int nf = 0; nf < 4; nf++) {
            const int n = n0 + wn + nf * 8 + (lane & 3) * 2;
            if (n < DA_) {
                const float bz0 = bias[n], bz1 = bias[n + 1];
                float2 o0, o1;
                o0.x = tanhf(tanhf(acc[mi][nf][0] + bz0) * xq0[n]);
                o0.y = tanhf(tanhf(acc[mi][nf][1] + bz1) * xq0[n + 1]);
                o1.x = tanhf(tanhf(acc[mi][nf][2] + bz0) * xq1[n]);
                o1.y = tanhf(tanhf(acc[mi][nf][3] + bz1) * xq1[n + 1]);
                *(float2*)&C[(size_t)r0 * DA_ + n] = o0;
                *(float2*)&C[(size_t)r1 * DA_ + n] = o1;
            }
        }
    }
}

// ---------------------------------------------------------------------------
// Small tiled GEMM: 64x64 tile, BK=16, 256 threads, 4x4 per thread.
// MODE 1: C = tanh(acc + bias);  MODE 2: A = A*extra elementwise, C = acc+bias
// ---------------------------------------------------------------------------
template<int MODE>
__global__ void gemm64(const float* __restrict__ A,
                       const float* __restrict__ W,
                       const float* __restrict__ bias,
                       const float* __restrict__ extra,
                       float* __restrict__ C,
                       int M, int N, int K, int lda, int ldc,
                       long aBS, long wBS, long bBS, long cBS)
{
    const int g = blockIdx.z;
    A    += (long)g * aBS;
    W    += (long)g * wBS;
    bias += (long)g * bBS;
    C    += (long)g * cBS;

    __shared__ float As[16][64];
    __shared__ float Bs[16][64];

    const int tid = threadIdx.x;
    const int ty  = tid >> 4;
    const int tx  = tid & 15;
    const int m0  = blockIdx.y * 64;
    const int n0  = blockIdx.x * 64;

    float acc[4][4];
#pragma unroll
    for (int i = 0; i < 4; i++)
#pragma unroll
        for (int j = 0; j < 4; j++) acc[i][j] = 0.f;

    for (int k0 = 0; k0 < K; k0 += 16) {
#pragma unroll
        for (int i = 0; i < 4; i++) {
            int e = i * 256 + tid;
            int m = e & 63, k = e >> 6;
            int mg = m0 + m;
            float v = 0.f;
            if (mg < M) {
                long idx = (long)mg * lda + k0 + k;
                v = A[idx];
                if (MODE == 2) v *= extra[idx];
            }
            As[k][m] = v;
        }
#pragma unroll
        for (int i = 0; i < 4; i++) {
            int e = i * 256 + tid;
            int k = e & 15, n = e >> 4;
            int ng = n0 + n;
            Bs[k][n] = (ng < N) ? W[(long)ng * K + k0 + k] : 0.f;
        }
        __syncthreads();

#pragma unroll
        for (int kk = 0; kk < 16; kk++) {
            float a[4], b[4];
#pragma unroll
            for (int i = 0; i < 4; i++) a[i] = As[kk][ty * 4 + i];
#pragma unroll
            for (int j = 0; j < 4; j++) b[j] = Bs[kk][tx * 4 + j];
#pragma unroll
            for (int i = 0; i < 4; i++)
#pragma unroll
                for (int j = 0; j < 4; j++) acc[i][j] += a[i] * b[j];
        }
        __syncthreads();
    }

#pragma unroll
    for (int i = 0; i < 4; i++) {
        int mg = m0 + ty * 4 + i;
        if (mg >= M) continue;
#pragma unroll
        for (int j = 0; j < 4; j++) {
            int n = n0 + tx * 4 + j;
            if (n >= N) continue;
            float v = acc[i][j] + bias[n];
            C[(long)mg * ldc + n] = (MODE == 1) ? tanhf(v) : v;
        }
    }
}

// wgt[b,g,n] = sum_d xatt[b,n,d]*Watt[g,d] + batt[g]  (one warp per (b,n))
__global__ void wgt_kernel(const float* __restrict__ xatt,
                           const float* __restrict__ Watt,
                           const float* __restrict__ batt,
                           float* __restrict__ out)
{
    int w    = (blockIdx.x * blockDim.x + threadIdx.x) >> 5;
    int lane = threadIdx.x & 31;
    if (w >= MROWS) return;
    int b = w / WH_, n = w - b * WH_;
    const float* xr = xatt + (long)w * DA_;
    float s0 = 0.f, s1 = 0.f;
    for (int d = lane; d < DA_; d += 32) {
        float x = xr[d];
        s0 += x * Watt[d];
        s1 += x * Watt[DA_ + d];
    }
#pragma unroll
    for (int o = 16; o > 0; o >>= 1) {
        s0 += __shfl_down_sync(0xffffffffu, s0, o);
        s1 += __shfl_down_sync(0xffffffffu, s1, o);
    }
    if (lane == 0) {
        out[((long)b * G_ + 0) * WH_ + n] = s0 + batt[0];
        out[((long)b * G_ + 1) * WH_ + n] = s1 + batt[1];
    }
}

// softmax over 196 per (b,g)
__global__ void softmax196(const float* __restrict__ wgt, float* __restrict__ att)
{
    __shared__ float red[256];
    int bg = blockIdx.x;
    int t  = threadIdx.x;
    const float* in = wgt + (long)bg * WH_;
    float v = (t < WH_) ? in[t] : -1e30f;
    red[t] = v; __syncthreads();
    for (int s = 128; s > 0; s >>= 1) {
        if (t < s) red[t] = fmaxf(red[t], red[t + s]);
        __syncthreads();
    }
    float mx = red[0]; __syncthreads();
    float e = (t < WH_) ? expf(v - mx) : 0.f;
    red[t] = e; __syncthreads();
    for (int s = 128; s > 0; s >>= 1) {
        if (t < s) red[t] += red[t + s];
        __syncthreads();
    }
    float inv = 1.f / red[0];
    if (t < WH_) att[(long)bg * WH_ + t] = e * inv;
}

// v_att[b,g,d] = sum_n att[b,g,n] * input_v[b,d,n]
__global__ void vatt_kernel(const float* __restrict__ v,
                            const float* __restrict__ att,
                            float* __restrict__ vatt)
{
    __shared__ float a0[WH_], a1[WH_];
    int b = blockIdx.x;
    int t = threadIdx.x;
    if (t < WH_) {
        a0[t] = att[((long)b * G_ + 0) * WH_ + t];
        a1[t] = att[((long)b * G_ + 1) * WH_ + t];
    }
    __syncthreads();
    int lane = t & 31, dd = t >> 5;
    int d = blockIdx.y * 8 + dd;
    const float* row = v + ((long)b * DV_ + d) * WH_;
    float s0 = 0.f, s1 = 0.f;
    for (int n = lane; n < WH_; n += 32) {
        float x = row[n];
        s0 += x * a0[n];
        s1 += x * a1[n];
    }
#pragma unroll
    for (int o = 16; o > 0; o >>= 1) {
        s0 += __shfl_down_sync(0xffffffffu, s0, o);
        s1 += __shfl_down_sync(0xffffffffu, s1, o);
    }
    if (lane == 0) {
        vatt[((long)b * G_ + 0) * DV_ + d] = s0;
        vatt[((long)b * G_ + 1) * DV_ + d] = s1;
    }
}

// ---------------------------------------------------------------------------
extern "C" void kernel_launch(void* const* d_in, const int* in_sizes, int n_in,
                              void* d_out, int out_size)
{
    const float* input_q = (const float*)d_in[0];
    const float* input_v = (const float*)d_in[1];
    const float* Wv_att  = (const float*)d_in[2];
    const float* bv_att  = (const float*)d_in[3];
    const float* Wq_att  = (const float*)d_in[4];
    const float* bq_att  = (const float*)d_in[5];
    const float* Watt    = (const float*)d_in[6];
    const float* batt    = (const float*)d_in[7];
    const float* Wv_fus  = (const float*)d_in[8];
    const float* bv_fus  = (const float*)d_in[9];
    const float* Wq_fus  = (const float*)d_in[10];
    const float* bq_fus  = (const float*)d_in[11];
    const float* Wc      = (const float*)d_in[12];
    const float* bc      = (const float*)d_in[13];

    float* out     = (float*)d_out;
    float* wgt_out = out + B_ * NC_;

    float *xatt, *xq, *att, *vatt, *vfus, *qfus;
    cudaGetSymbolAddress((void**)&xatt, g_xatt);
    cudaGetSymbolAddress((void**)&xq,   g_xq);
    cudaGetSymbolAddress((void**)&att,  g_att);
    cudaGetSymbolAddress((void**)&vatt, g_vatt);
    cudaGetSymbolAddress((void**)&vfus, g_vfus);
    cudaGetSymbolAddress((void**)&qfus, g_qfus);

    cudaFuncSetAttribute(gemm1_mma, cudaFuncAttributeMaxDynamicSharedMemorySize, SMEM_G1);

    // 0) bf16 hi/lo prepack of GEMM1 operands
    pack_W<<<((size_t)DA_ * DV_ / 4 + 255) / 256, 256>>>(Wv_att);
    pack_A<<<dim3(7, DV_ / 32, B_), dim3(32, 8)>>>(input_v);

    // 1) xq = tanh(input_q @ Wq_att^T + bq_att)   [64, 1200]
    gemm64<1><<<dim3((DA_ + 63) / 64, 1, 1), 256>>>(
        input_q, Wq_att, bq_att, nullptr, xq,
        B_, DA_, DQ_, DQ_, DA_, 0, 0, 0, 0);

    // 2) xatt via mma.sync bf16 (3x split)        [12544, 1200]
    gemm1_mma<<<dim3((DA_ + 127) / 128, MROWS / 128), 256, SMEM_G1>>>(bv_att, xq, xatt);

    // 3) wgt (part of output)                     [64, 2, 196]
    wgt_kernel<<<(MROWS * 32 + 255) / 256, 256>>>(xatt, Watt, batt, wgt_out);

    // 4) att = softmax(wgt)
    softmax196<<<B_ * G_, 256>>>(wgt_out, att);

    // 5) v_att = att @ V                          [64, 2, 2048]
    vatt_kernel<<<dim3(B_, DV_ / 8), 256>>>(input_v, att, vatt);

    // 6) v_fus = tanh(v_att @ Wv_fus^T + b)       [64, 2400]
    gemm64<1><<<dim3((DH_ + 63) / 64, 1, G_), 256>>>(
        vatt, Wv_fus, bv_fus, nullptr, vfus,
        B_, DH_, DV_, G_ * DV_, G_ * DH_,
        (long)DV_, (long)DH_ * DV_, (long)DH_, (long)DH_);

    // 7) q_fus = tanh(input_q @ Wq_fus^T + b)     [64, 2400]
    gemm64<1><<<dim3((G_ * DH_ + 63) / 64, 1, 1), 256>>>(
        input_q, Wq_fus, bq_fus, nullptr, qfus,
        B_, G_ * DH_, DQ_, DQ_, G_ * DH_, 0, 0, 0, 0);

    // 8) x = (v_fus * q_fus) @ Wc^T + bc          [64, 3000]
    gemm64<2><<<dim3((NC_ + 63) / 64, 1, 1), 256>>>(
        vfus, Wc, bc, qfus, out,
        B_, NC_, G_ * DH_, G_ * DH_, NC_, 0, 0, 0, 0);
}

// round 7
// speedup vs baseline: 2.7297x; 1.3976x over previous
#include <cuda_runtime.h>
#include <cuda_bf16.h>
#include <math.h>
#include <cstdint>

// Problem dims
#define B_   64
#define DV_  2048
#define WH_  196
#define DQ_  2400
#define DA_  1200
#define G_   2
#define DH_  1200
#define NC_  3000
#define MROWS (B_*WH_)   // 12544

// ---------------- scratch (device globals; no allocation allowed) ----------
__device__ float g_xatt[MROWS * DA_];        // [12544, 1200]
__device__ float g_xq  [B_ * DA_];
__device__ float g_att [B_ * G_ * WH_];
__device__ float g_vatt[B_ * G_ * DV_];
__device__ float g_vfus[B_ * G_ * DH_];
__device__ float g_qfus[B_ * G_ * DH_];
__device__ float g_hfus[B_ * G_ * DH_];
// bf16 split operands for GEMM1 (A = V transposed to [M,K] K-major)
__device__ __nv_bfloat16 g_Ahi[(size_t)MROWS * DV_];
__device__ __nv_bfloat16 g_Alo[(size_t)MROWS * DV_];
__device__ __nv_bfloat16 g_Bhi[(size_t)DA_ * DV_];
__device__ __nv_bfloat16 g_Blo[(size_t)DA_ * DV_];

// ============================ PTX helpers ==================================
__device__ __forceinline__ uint32_t smem_u32(const void* p) {
    uint32_t a;
    asm("{ .reg .u64 t; cvta.to.shared.u64 t, %1; cvt.u32.u64 %0, t; }" : "=r"(a) : "l"(p));
    return a;
}
__device__ __forceinline__ void cp16(uint32_t dst, const void* src) {
    asm volatile("cp.async.cg.shared.global [%0], [%1], 16;" :: "r"(dst), "l"(src));
}
#define CP_COMMIT() asm volatile("cp.async.commit_group;" ::: "memory")
#define CP_WAIT(n)  asm volatile("cp.async.wait_group %0;" :: "n"(n) : "memory")

__device__ __forceinline__ void ldsm_x4(uint32_t* r, uint32_t addr) {
    asm volatile("ldmatrix.sync.aligned.m8n8.x4.shared.b16 {%0,%1,%2,%3}, [%4];"
                 : "=r"(r[0]), "=r"(r[1]), "=r"(r[2]), "=r"(r[3]) : "r"(addr));
}
__device__ __forceinline__ void mma_bf16(float* c, const uint32_t* a, const uint32_t* b) {
    asm volatile("mma.sync.aligned.m16n8k16.row.col.f32.bf16.bf16.f32 "
                 "{%0,%1,%2,%3}, {%4,%5,%6,%7}, {%8,%9}, {%0,%1,%2,%3};"
                 : "+f"(c[0]), "+f"(c[1]), "+f"(c[2]), "+f"(c[3])
                 : "r"(a[0]), "r"(a[1]), "r"(a[2]), "r"(a[3]), "r"(b[0]), "r"(b[1]));
}

// ============================ prepack kernels ==============================
__device__ __forceinline__ void split_bf16(float x, __nv_bfloat16& hi, __nv_bfloat16& lo) {
    hi = __float2bfloat16(x);
    lo = __float2bfloat16(x - __bfloat162float(hi));
}

// Wv_att [1200, 2048] row-major (K contiguous) -> hi/lo, same layout
__global__ void pack_W(const float* __restrict__ W) {
    size_t i = (size_t)blockIdx.x * blockDim.x + threadIdx.x;
    size_t total = (size_t)DA_ * DV_ / 4;
    if (i >= total) return;
    const float4 v = ((const float4*)W)[i];
    __nv_bfloat16 h0, l0, h1, l1, h2, l2, h3, l3;
    split_bf16(v.x, h0, l0); split_bf16(v.y, h1, l1);
    split_bf16(v.z, h2, l2); split_bf16(v.w, h3, l3);
    __nv_bfloat162* Hi = (__nv_bfloat162*)g_Bhi;
    __nv_bfloat162* Lo = (__nv_bfloat162*)g_Blo;
    Hi[i * 2 + 0] = __nv_bfloat162(h0, h1); Hi[i * 2 + 1] = __nv_bfloat162(h2, h3);
    Lo[i * 2 + 0] = __nv_bfloat162(l0, l1); Lo[i * 2 + 1] = __nv_bfloat162(l2, l3);
}

// input_v [64, 2048, 196] -> A[m=(b,ns)][k] bf16 hi/lo (transpose via smem tile)
__global__ void pack_A(const float* __restrict__ V) {
    __shared__ float tile[32][33];
    int ns0 = blockIdx.x * 32;
    int k0  = blockIdx.y * 32;
    int b   = blockIdx.z;
    int tx = threadIdx.x, ty = threadIdx.y;   // (32, 8)
#pragma unroll
    for (int r = 0; r < 4; r++) {
        int kl = ty + r * 8;
        int ns = ns0 + tx;
        float v = (ns < WH_) ? V[((size_t)b * DV_ + (k0 + kl)) * WH_ + ns] : 0.f;
        tile[kl][tx] = v;
    }
    __syncthreads();
#pragma unroll
    for (int r = 0; r < 4; r++) {
        int nsl = ty + r * 8;
        int ns = ns0 + nsl;
        if (ns < WH_) {
            size_t m = (size_t)b * WH_ + ns;
            float v = tile[tx][nsl];
            __nv_bfloat16 hi, lo;
            split_bf16(v, hi, lo);
            g_Ahi[m * DV_ + k0 + tx] = hi;
            g_Alo[m * DV_ + k0 + tx] = lo;
        }
    }
}

// ============================ GEMM1 (mma.sync bf16, 3x split) ==============
// C[m,n] = tanh( tanh( sum_k A[m,k]*W[n,k] + bias[n] ) * xq[b,n] )
// Block 128x128x32, 8 warps (2m x 4n), warp 64x32. 3-stage cp.async pipeline,
// ONE __syncthreads per k-stage (loads issued post-compute target the buffer
// retired two stages earlier).
#define APART  10240           // 128 * 80
#define STG_B  20480
#define STAGE  40960
#define NBUF   3
#define SMEM_G1 (NBUF * STAGE)  // 122880

__global__ void __launch_bounds__(256, 1)
gemm1_mma(const float* __restrict__ bias, const float* __restrict__ xq,
          float* __restrict__ C)
{
    extern __shared__ char sm[];
    const uint32_t sb = smem_u32(sm);
    const int tid = threadIdx.x, warp = tid >> 5, lane = tid & 31;
    const int m0 = blockIdx.y * 128;
    const int n0 = blockIdx.x * 128;
    const int wm = (warp & 1) * 64;
    const int wn = (warp >> 1) * 32;

    float acc[4][4][4];
#pragma unroll
    for (int mi = 0; mi < 4; mi++)
#pragma unroll
        for (int nf = 0; nf < 4; nf++)
#pragma unroll
            for (int e = 0; e < 4; e++) acc[mi][nf][e] = 0.f;

    const int r_a = tid >> 2, c_a = tid & 3;

    auto load_stage = [&](int ks, int buf) {
        const int k0 = ks * 32;
        const uint32_t dstA = sb + buf * STAGE;
        const uint32_t dstB = dstA + STG_B;
#pragma unroll
        for (int part = 0; part < 2; part++) {
            const __nv_bfloat16* src = part ? g_Alo : g_Ahi;
#pragma unroll
            for (int i = 0; i < 2; i++) {
                int row = r_a + i * 64;
                cp16(dstA + part * APART + row * 80 + c_a * 16,
                     src + (size_t)(m0 + row) * DV_ + k0 + c_a * 8);
            }
        }
#pragma unroll
        for (int part = 0; part < 2; part++) {
            const __nv_bfloat16* src = part ? g_Blo : g_Bhi;
#pragma unroll
            for (int i = 0; i < 2; i++) {
                int row = r_a + i * 64;
                int rg = n0 + row; if (rg >= DA_) rg = DA_ - 1;
                cp16(dstB + part * APART + row * 80 + c_a * 16,
                     src + (size_t)rg * DV_ + k0 + c_a * 8);
            }
        }
    };

    load_stage(0, 0); CP_COMMIT();
    load_stage(1, 1); CP_COMMIT();

    const int NST = DV_ / 32;   // 64
    for (int ks = 0; ks < NST; ks++) {
        const int buf = ks % NBUF;
        if (ks == NST - 1) { CP_WAIT(0); } else { CP_WAIT(1); }
        __syncthreads();

        const uint32_t Ab = sb + buf * STAGE;
        const uint32_t Bb = Ab + STG_B;
#pragma unroll
        for (int kb2 = 0; kb2 < 2; kb2++) {
            const int kb = kb2 * 16;
            uint32_t a_hi[4][4], a_lo[4][4], b_hi[2][4], b_lo[2][4];
            const uint32_t aAddr = Ab + (wm + (lane & 15)) * 80 + kb * 2 + ((lane >> 4) << 4);
#pragma unroll
            for (int mi = 0; mi < 4; mi++) {
                ldsm_x4(a_hi[mi], aAddr + mi * 16 * 80);
                ldsm_x4(a_lo[mi], aAddr + APART + mi * 16 * 80);
            }
            const uint32_t bAddr = Bb + (wn + ((lane >> 4) << 3) + (lane & 7)) * 80
                                 + (kb + ((lane >> 3) & 1) * 8) * 2;
#pragma unroll
            for (int nj = 0; nj < 2; nj++) {
                ldsm_x4(b_hi[nj], bAddr + nj * 16 * 80);
                ldsm_x4(b_lo[nj], bAddr + APART + nj * 16 * 80);
            }
#pragma unroll
            for (int mi = 0; mi < 4; mi++)
#pragma unroll
                for (int nf = 0; nf < 4; nf++) {
                    const uint32_t* bh = &b_hi[nf >> 1][(nf & 1) * 2];
                    const uint32_t* bl = &b_lo[nf >> 1][(nf & 1) * 2];
                    mma_bf16(acc[mi][nf], a_hi[mi], bh);
                    mma_bf16(acc[mi][nf], a_hi[mi], bl);
                    mma_bf16(acc[mi][nf], a_lo[mi], bh);
                }
        }
        // issue loads for stage ks+2 into buffer (ks+2)%3 == (ks-1)%3, whose
        // compute finished before this iteration's __syncthreads.
        if (ks + 2 < NST) { load_stage(ks + 2, (ks + 2) % NBUF); CP_COMMIT(); }
    }

    // --- fused epilogue: tanh(tanh(acc+bias)*xq), float2 stores ---
#pragma unroll
    for (int mi = 0; mi < 4; mi++) {
        const int r0 = m0 + wm + mi * 16 + (lane >> 2);
        const int r1 = r0 + 8;
        const int b0 = r0 / WH_, b1 = r1 / WH_;
        const float* xq0 = xq + (size_t)b0 * DA_;
        const float* xq1 = xq + (size_t)b1 * DA_;
#pragma unroll
        for (int nf = 0; nf < 4; nf++) {
            const int n = n0 + wn + nf * 8 + (lane & 3) * 2;
            if (n < DA_) {
                const float bz0 = bias[n], bz1 = bias[n + 1];
                float2 o0, o1;
                o0.x = tanhf(tanhf(acc[mi][nf][0] + bz0) * xq0[n]);
                o0.y = tanhf(tanhf(acc[mi][nf][1] + bz1) * xq0[n + 1]);
                o1.x = tanhf(tanhf(acc[mi][nf][2] + bz0) * xq1[n]);
                o1.y = tanhf(tanhf(acc[mi][nf][3] + bz1) * xq1[n + 1]);
                *(float2*)&C[(size_t)r0 * DA_ + n] = o0;
                *(float2*)&C[(size_t)r1 * DA_ + n] = o1;
            }
        }
    }
}

// ---------------------------------------------------------------------------
// Small GEMM (M=64 exactly): 64xN tile, BK=32, 256 threads, 4x4/thread.
// Coalesced k-fast loads + depth-2 register prefetch (zero exposed latency).
// MODE 1: C = tanh(acc+bias);  MODE 3: C = acc+bias.
// ---------------------------------------------------------------------------
template<int MODE>
__global__ void gemm64p(const float* __restrict__ A,
                        const float* __restrict__ W,
                        const float* __restrict__ bias,
                        float* __restrict__ C,
                        int Ntot, int K, int lda, int ldc,
                        long aBS, long wBS, long bBS, long cBS)
{
    const int g = blockIdx.z;
    A    += (long)g * aBS;
    W    += (long)g * wBS;
    bias += (long)g * bBS;
    C    += (long)g * cBS;

    __shared__ float As[64][33];
    __shared__ float Bs[64][33];

    const int tid = threadIdx.x;
    const int ty  = tid >> 4;      // 0..15
    const int tx  = tid & 15;      // 0..15
    const int n0  = blockIdx.x * 64;
    const int lr  = tid >> 5;      // 0..7
    const int lk  = tid & 31;      // 0..31

    auto fetchA = [&](int k0, float* r) {
#pragma unroll
        for (int i = 0; i < 8; i++) {
            int row = i * 8 + lr;               // M = 64 always full
            r[i] = A[(long)row * lda + k0 + lk];
        }
    };
    auto fetchB = [&](int k0, float* r) {
#pragma unroll
        for (int i = 0; i < 8; i++) {
            int row = i * 8 + lr;
            int ng = n0 + row; if (ng >= Ntot) ng = Ntot - 1;   // clamp; masked at store
            r[i] = W[(long)ng * K + k0 + lk];
        }
    };

    float rA[2][8], rB[2][8];
    fetchA(0, rA[0]); fetchB(0, rB[0]);
    const int nst = K / 32;
    if (nst > 1) { fetchA(32, rA[1]); fetchB(32, rB[1]); }

    float acc[4][4];
#pragma unroll
    for (int i = 0; i < 4; i++)
#pragma unroll
        for (int j = 0; j < 4; j++) acc[i][j] = 0.f;

    for (int s = 0; s < nst; s++) {
        float* cA = rA[s & 1];
        float* cB = rB[s & 1];
        __syncthreads();               // prior compute done before smem overwrite
#pragma unroll
        for (int i = 0; i < 8; i++) {
            As[i * 8 + lr][lk] = cA[i];
            Bs[i * 8 + lr][lk] = cB[i];
        }
        if (s + 2 < nst) { fetchA((s + 2) * 32, rA[s & 1]); fetchB((s + 2) * 32, rB[s & 1]); }
        __syncthreads();
#pragma unroll
        for (int kk = 0; kk < 32; kk++) {
            float a[4], b[4];
#pragma unroll
            for (int i = 0; i < 4; i++) a[i] = As[ty * 4 + i][kk];
#pragma unroll
            for (int j = 0; j < 4; j++) b[j] = Bs[tx * 4 + j][kk];
#pragma unroll
            for (int i = 0; i < 4; i++)
#pragma unroll
                for (int j = 0; j < 4; j++) acc[i][j] += a[i] * b[j];
        }
    }

#pragma unroll
    for (int i = 0; i < 4; i++) {
        int m = ty * 4 + i;
#pragma unroll
        for (int j = 0; j < 4; j++) {
            int n = n0 + tx * 4 + j;
            if (n >= Ntot) continue;
            float v = acc[i][j] + bias[n];
            C[(long)m * ldc + n] = (MODE == 1) ? tanhf(v) : v;
        }
    }
}

// hfus = vfus * qfus (elementwise)
__global__ void fuse_mul(const float* __restrict__ a, const float* __restrict__ b,
                         float* __restrict__ o, int n) {
    int i = blockIdx.x * blockDim.x + threadIdx.x;
    if (i < n) o[i] = a[i] * b[i];
}

// wgt[b,g,n] = sum_d xatt[b,n,d]*Watt[g,d] + batt[g]  (one warp per (b,n))
__global__ void wgt_kernel(const float* __restrict__ xatt,
                           const float* __restrict__ Watt,
                           const float* __restrict__ batt,
                           float* __restrict__ out)
{
    int w    = (blockIdx.x * blockDim.x + threadIdx.x) >> 5;
    int lane = threadIdx.x & 31;
    if (w >= MROWS) return;
    int b = w / WH_, n = w - b * WH_;
    const float* xr = xatt + (long)w * DA_;
    float s0 = 0.f, s1 = 0.f;
    for (int d = lane; d < DA_; d += 32) {
        float x = xr[d];
        s0 += x * Watt[d];
        s1 += x * Watt[DA_ + d];
    }
#pragma unroll
    for (int o = 16; o > 0; o >>= 1) {
        s0 += __shfl_down_sync(0xffffffffu, s0, o);
        s1 += __shfl_down_sync(0xffffffffu, s1, o);
    }
    if (lane == 0) {
        out[((long)b * G_ + 0) * WH_ + n] = s0 + batt[0];
        out[((long)b * G_ + 1) * WH_ + n] = s1 + batt[1];
    }
}

// softmax over 196 per (b,g)
__global__ void softmax196(const float* __restrict__ wgt, float* __restrict__ att)
{
    __shared__ float red[256];
    int bg = blockIdx.x;
    int t  = threadIdx.x;
    const float* in = wgt + (long)bg * WH_;
    float v = (t < WH_) ? in[t] : -1e30f;
    red[t] = v; __syncthreads();
    for (int s = 128; s > 0; s >>= 1) {
        if (t < s) red[t] = fmaxf(red[t], red[t + s]);
        __syncthreads();
    }
    float mx = red[0]; __syncthreads();
    float e = (t < WH_) ? expf(v - mx) : 0.f;
    red[t] = e; __syncthreads();
    for (int s = 128; s > 0; s >>= 1) {
        if (t < s) red[t] += red[t + s];
        __syncthreads();
    }
    float inv = 1.f / red[0];
    if (t < WH_) att[(long)bg * WH_ + t] = e * inv;
}

// v_att[b,g,d] = sum_n att[b,g,n] * input_v[b,d,n]
__global__ void vatt_kernel(const float* __restrict__ v,
                            const float* __restrict__ att,
                            float* __restrict__ vatt)
{
    __shared__ float a0[WH_], a1[WH_];
    int b = blockIdx.x;
    int t = threadIdx.x;
    if (t < WH_) {
        a0[t] = att[((long)b * G_ + 0) * WH_ + t];
        a1[t] = att[((long)b * G_ + 1) * WH_ + t];
    }
    __syncthreads();
    int lane = t & 31, dd = t >> 5;
    int d = blockIdx.y * 8 + dd;
    const float* row = v + ((long)b * DV_ + d) * WH_;
    float s0 = 0.f, s1 = 0.f;
    for (int n = lane; n < WH_; n += 32) {
        float x = row[n];
        s0 += x * a0[n];
        s1 += x * a1[n];
    }
#pragma unroll
    for (int o = 16; o > 0; o >>= 1) {
        s0 += __shfl_down_sync(0xffffffffu, s0, o);
        s1 += __shfl_down_sync(0xffffffffu, s1, o);
    }
    if (lane == 0) {
        vatt[((long)b * G_ + 0) * DV_ + d] = s0;
        vatt[((long)b * G_ + 1) * DV_ + d] = s1;
    }
}

// ---------------------------------------------------------------------------
extern "C" void kernel_launch(void* const* d_in, const int* in_sizes, int n_in,
                              void* d_out, int out_size)
{
    const float* input_q = (const float*)d_in[0];
    const float* input_v = (const float*)d_in[1];
    const float* Wv_att  = (const float*)d_in[2];
    const float* bv_att  = (const float*)d_in[3];
    const float* Wq_att  = (const float*)d_in[4];
    const float* bq_att  = (const float*)d_in[5];
    const float* Watt    = (const float*)d_in[6];
    const float* batt    = (const float*)d_in[7];
    const float* Wv_fus  = (const float*)d_in[8];
    const float* bv_fus  = (const float*)d_in[9];
    const float* Wq_fus  = (const float*)d_in[10];
    const float* bq_fus  = (const float*)d_in[11];
    const float* Wc      = (const float*)d_in[12];
    const float* bc      = (const float*)d_in[13];

    float* out     = (float*)d_out;
    float* wgt_out = out + B_ * NC_;

    float *xatt, *xq, *att, *vatt, *vfus, *qfus, *hfus;
    cudaGetSymbolAddress((void**)&xatt, g_xatt);
    cudaGetSymbolAddress((void**)&xq,   g_xq);
    cudaGetSymbolAddress((void**)&att,  g_att);
    cudaGetSymbolAddress((void**)&vatt, g_vatt);
    cudaGetSymbolAddress((void**)&vfus, g_vfus);
    cudaGetSymbolAddress((void**)&qfus, g_qfus);
    cudaGetSymbolAddress((void**)&hfus, g_hfus);

    cudaFuncSetAttribute(gemm1_mma, cudaFuncAttributeMaxDynamicSharedMemorySize, SMEM_G1);

    // 0) bf16 hi/lo prepack of GEMM1 operands
    pack_W<<<((size_t)DA_ * DV_ / 4 + 255) / 256, 256>>>(Wv_att);
    pack_A<<<dim3(7, DV_ / 32, B_), dim3(32, 8)>>>(input_v);

    // 1) xq = tanh(input_q @ Wq_att^T + bq_att)   [64, 1200]
    gemm64p<1><<<dim3((DA_ + 63) / 64, 1, 1), 256>>>(
        input_q, Wq_att, bq_att, xq, DA_, DQ_, DQ_, DA_, 0, 0, 0, 0);

    // 2) xatt via mma.sync bf16 (3x split)        [12544, 1200]
    gemm1_mma<<<dim3((DA_ + 127) / 128, MROWS / 128), 256, SMEM_G1>>>(bv_att, xq, xatt);

    // 3) wgt (part of output)                     [64, 2, 196]
    wgt_kernel<<<(MROWS * 32 + 255) / 256, 256>>>(xatt, Watt, batt, wgt_out);

    // 4) att = softmax(wgt)
    softmax196<<<B_ * G_, 256>>>(wgt_out, att);

    // 5) v_att = att @ V                          [64, 2, 2048]
    vatt_kernel<<<dim3(B_, DV_ / 8), 256>>>(input_v, att, vatt);

    // 6) v_fus = tanh(v_att @ Wv_fus^T + b)       [64, 2400]
    gemm64p<1><<<dim3((DH_ + 63) / 64, 1, G_), 256>>>(
        vatt, Wv_fus, bv_fus, vfus,
        DH_, DV_, G_ * DV_, G_ * DH_,
        (long)DV_, (long)DH_ * DV_, (long)DH_, (long)DH_);

    // 7) q_fus = tanh(input_q @ Wq_fus^T + b)     [64, 2400]
    gemm64p<1><<<dim3((G_ * DH_ + 63) / 64, 1, 1), 256>>>(
        input_q, Wq_fus, bq_fus, qfus, G_ * DH_, DQ_, DQ_, G_ * DH_, 0, 0, 0, 0);

    // 7b) hfus = vfus * qfus
    fuse_mul<<<(B_ * G_ * DH_ + 255) / 256, 256>>>(vfus, qfus, hfus, B_ * G_ * DH_);

    // 8) x = hfus @ Wc^T + bc                     [64, 3000]
    gemm64p<3><<<dim3((NC_ + 63) / 64, 1, 1), 256>>>(
        hfus, Wc, bc, out, NC_, G_ * DH_, G_ * DH_, NC_, 0, 0, 0, 0);
}

// round 8
// speedup vs baseline: 4.1528x; 1.5213x over previous
#include <cuda_runtime.h>
#include <cuda_bf16.h>
#include <math.h>
#include <cstdint>

// Problem dims
#define B_   64
#define DV_  2048
#define WH_  196
#define DQ_  2400
#define DA_  1200
#define G_   2
#define DH_  1200
#define NC_  3000
#define MROWS (B_*WH_)   // 12544

// ---------------- scratch (device globals; no allocation allowed) ----------
__device__ float g_xatt[MROWS * DA_];        // [12544, 1200]
__device__ float g_xq  [B_ * DA_];
__device__ float g_att [B_ * G_ * WH_];
__device__ float g_vatt[B_ * G_ * DV_];
__device__ float g_vfus[B_ * G_ * DH_];
__device__ float g_qfus[B_ * G_ * DH_];
__device__ float g_hfus[B_ * G_ * DH_];
__device__ float g_part[2 * 8 * 64 * NC_];   // split-K partials (max case)
// bf16 split operands for GEMM1 (A = V transposed to [M,K] K-major)
__device__ __nv_bfloat16 g_Ahi[(size_t)MROWS * DV_];
__device__ __nv_bfloat16 g_Alo[(size_t)MROWS * DV_];
__device__ __nv_bfloat16 g_Bhi[(size_t)DA_ * DV_];
__device__ __nv_bfloat16 g_Blo[(size_t)DA_ * DV_];

// ============================ PTX helpers ==================================
__device__ __forceinline__ uint32_t smem_u32(const void* p) {
    uint32_t a;
    asm("{ .reg .u64 t; cvta.to.shared.u64 t, %1; cvt.u32.u64 %0, t; }" : "=r"(a) : "l"(p));
    return a;
}
__device__ __forceinline__ void cp16(uint32_t dst, const void* src) {
    asm volatile("cp.async.cg.shared.global [%0], [%1], 16;" :: "r"(dst), "l"(src));
}
#define CP_COMMIT() asm volatile("cp.async.commit_group;" ::: "memory")
#define CP_WAIT(n)  asm volatile("cp.async.wait_group %0;" :: "n"(n) : "memory")

__device__ __forceinline__ void ldsm_x4(uint32_t* r, uint32_t addr) {
    asm volatile("ldmatrix.sync.aligned.m8n8.x4.shared.b16 {%0,%1,%2,%3}, [%4];"
                 : "=r"(r[0]), "=r"(r[1]), "=r"(r[2]), "=r"(r[3]) : "r"(addr));
}
__device__ __forceinline__ void mma_bf16(float* c, const uint32_t* a, const uint32_t* b) {
    asm volatile("mma.sync.aligned.m16n8k16.row.col.f32.bf16.bf16.f32 "
                 "{%0,%1,%2,%3}, {%4,%5,%6,%7}, {%8,%9}, {%0,%1,%2,%3};"
                 : "+f"(c[0]), "+f"(c[1]), "+f"(c[2]), "+f"(c[3])
                 : "r"(a[0]), "r"(a[1]), "r"(a[2]), "r"(a[3]), "r"(b[0]), "r"(b[1]));
}

// ============================ prepack kernels ==============================
__device__ __forceinline__ void split_bf16(float x, __nv_bfloat16& hi, __nv_bfloat16& lo) {
    hi = __float2bfloat16(x);
    lo = __float2bfloat16(x - __bfloat162float(hi));
}

__global__ void pack_W(const float* __restrict__ W) {
    size_t i = (size_t)blockIdx.x * blockDim.x + threadIdx.x;
    size_t total = (size_t)DA_ * DV_ / 4;
    if (i >= total) return;
    const float4 v = ((const float4*)W)[i];
    __nv_bfloat16 h0, l0, h1, l1, h2, l2, h3, l3;
    split_bf16(v.x, h0, l0); split_bf16(v.y, h1, l1);
    split_bf16(v.z, h2, l2); split_bf16(v.w, h3, l3);
    __nv_bfloat162* Hi = (__nv_bfloat162*)g_Bhi;
    __nv_bfloat162* Lo = (__nv_bfloat162*)g_Blo;
    Hi[i * 2 + 0] = __nv_bfloat162(h0, h1); Hi[i * 2 + 1] = __nv_bfloat162(h2, h3);
    Lo[i * 2 + 0] = __nv_bfloat162(l0, l1); Lo[i * 2 + 1] = __nv_bfloat162(l2, l3);
}

__global__ void pack_A(const float* __restrict__ V) {
    __shared__ float tile[32][33];
    int ns0 = blockIdx.x * 32;
    int k0  = blockIdx.y * 32;
    int b   = blockIdx.z;
    int tx = threadIdx.x, ty = threadIdx.y;   // (32, 8)
#pragma unroll
    for (int r = 0; r < 4; r++) {
        int kl = ty + r * 8;
        int ns = ns0 + tx;
        float v = (ns < WH_) ? V[((size_t)b * DV_ + (k0 + kl)) * WH_ + ns] : 0.f;
        tile[kl][tx] = v;
    }
    __syncthreads();
#pragma unroll
    for (int r = 0; r < 4; r++) {
        int nsl = ty + r * 8;
        int ns = ns0 + nsl;
        if (ns < WH_) {
            size_t m = (size_t)b * WH_ + ns;
            float v = tile[tx][nsl];
            __nv_bfloat16 hi, lo;
            split_bf16(v, hi, lo);
            g_Ahi[m * DV_ + k0 + tx] = hi;
            g_Alo[m * DV_ + k0 + tx] = lo;
        }
    }
}

// ============================ GEMM1 (mma.sync bf16, 3x split) ==============
// 128x128x32 block, 8 warps (2m x 4n), 4-stage cp.async pipeline, 1 sync/stage.
#define APART  10240           // 128 * 80
#define STG_B  20480
#define STAGE  40960
#define NBUF   4
#define SMEM_G1 (NBUF * STAGE)  // 163840

__global__ void __launch_bounds__(256, 1)
gemm1_mma(const float* __restrict__ bias, const float* __restrict__ xq,
          float* __restrict__ C)
{
    extern __shared__ char sm[];
    const uint32_t sb = smem_u32(sm);
    const int tid = threadIdx.x, warp = tid >> 5, lane = tid & 31;
    const int m0 = blockIdx.y * 128;
    const int n0 = blockIdx.x * 128;
    const int wm = (warp & 1) * 64;
    const int wn = (warp >> 1) * 32;

    float acc[4][4][4];
#pragma unroll
    for (int mi = 0; mi < 4; mi++)
#pragma unroll
        for (int nf = 0; nf < 4; nf++)
#pragma unroll
            for (int e = 0; e < 4; e++) acc[mi][nf][e] = 0.f;

    const int r_a = tid >> 2, c_a = tid & 3;

    auto load_stage = [&](int ks, int buf) {
        const int k0 = ks * 32;
        const uint32_t dstA = sb + buf * STAGE;
        const uint32_t dstB = dstA + STG_B;
#pragma unroll
        for (int part = 0; part < 2; part++) {
            const __nv_bfloat16* src = part ? g_Alo : g_Ahi;
#pragma unroll
            for (int i = 0; i < 2; i++) {
                int row = r_a + i * 64;
                cp16(dstA + part * APART + row * 80 + c_a * 16,
                     src + (size_t)(m0 + row) * DV_ + k0 + c_a * 8);
            }
        }
#pragma unroll
        for (int part = 0; part < 2; part++) {
            const __nv_bfloat16* src = part ? g_Blo : g_Bhi;
#pragma unroll
            for (int i = 0; i < 2; i++) {
                int row = r_a + i * 64;
                int rg = n0 + row; if (rg >= DA_) rg = DA_ - 1;
                cp16(dstB + part * APART + row * 80 + c_a * 16,
                     src + (size_t)rg * DV_ + k0 + c_a * 8);
            }
        }
    };

    load_stage(0, 0); CP_COMMIT();
    load_stage(1, 1); CP_COMMIT();
    load_stage(2, 2); CP_COMMIT();

    const int NST = DV_ / 32;   // 64
    for (int ks = 0; ks < NST; ks++) {
        const int buf = ks % NBUF;
        const int rem = NST - 1 - ks;            // groups committed beyond ks
        if (rem >= 2)      { CP_WAIT(2); }
        else if (rem == 1) { CP_WAIT(1); }
        else               { CP_WAIT(0); }
        __syncthreads();

        const uint32_t Ab = sb + buf * STAGE;
        const uint32_t Bb = Ab + STG_B;
#pragma unroll
        for (int kb2 = 0; kb2 < 2; kb2++) {
            const int kb = kb2 * 16;
            uint32_t a_hi[4][4], a_lo[4][4], b_hi[2][4], b_lo[2][4];
            const uint32_t aAddr = Ab + (wm + (lane & 15)) * 80 + kb * 2 + ((lane >> 4) << 4);
#pragma unroll
            for (int mi = 0; mi < 4; mi++) {
                ldsm_x4(a_hi[mi], aAddr + mi * 16 * 80);
                ldsm_x4(a_lo[mi], aAddr + APART + mi * 16 * 80);
            }
            const uint32_t bAddr = Bb + (wn + ((lane >> 4) << 3) + (lane & 7)) * 80
                                 + (kb + ((lane >> 3) & 1) * 8) * 2;
#pragma unroll
            for (int nj = 0; nj < 2; nj++) {
                ldsm_x4(b_hi[nj], bAddr + nj * 16 * 80);
                ldsm_x4(b_lo[nj], bAddr + APART + nj * 16 * 80);
            }
#pragma unroll
            for (int mi = 0; mi < 4; mi++)
#pragma unroll
                for (int nf = 0; nf < 4; nf++) {
                    const uint32_t* bh = &b_hi[nf >> 1][(nf & 1) * 2];
                    const uint32_t* bl = &b_lo[nf >> 1][(nf & 1) * 2];
                    mma_bf16(acc[mi][nf], a_hi[mi], bh);
                    mma_bf16(acc[mi][nf], a_hi[mi], bl);
                    mma_bf16(acc[mi][nf], a_lo[mi], bh);
                }
        }
        // loads for ks+3 -> buffer (ks+3)%4 == (ks-1)%4 (its compute done at ks-1)
        if (ks + 3 < NST) { load_stage(ks + 3, (ks + 3) % NBUF); CP_COMMIT(); }
    }

    // --- fused epilogue: tanh(tanh(acc+bias)*xq), float2 stores ---
#pragma unroll
    for (int mi = 0; mi < 4; mi++) {
        const int r0 = m0 + wm + mi * 16 + (lane >> 2);
        const int r1 = r0 + 8;
        const int b0 = r0 / WH_, b1 = r1 / WH_;
        const float* xq0 = xq + (size_t)b0 * DA_;
        const float* xq1 = xq + (size_t)b1 * DA_;
#pragma unroll
        for (int nf = 0; nf < 4; nf++) {
            const int n = n0 + wn + nf * 8 + (lane & 3) * 2;
            if (n < DA_) {
                const float bz0 = bias[n], bz1 = bias[n + 1];
                float2 o0, o1;
                o0.x = tanhf(tanhf(acc[mi][nf][0] + bz0) * xq0[n]);
                o0.y = tanhf(tanhf(acc[mi][nf][1] + bz1) * xq0[n + 1]);
                o1.x = tanhf(tanhf(acc[mi][nf][2] + bz0) * xq1[n]);
                o1.y = tanhf(tanhf(acc[mi][nf][3] + bz1) * xq1[n + 1]);
                *(float2*)&C[(size_t)r0 * DA_ + n] = o0;
                *(float2*)&C[(size_t)r1 * DA_ + n] = o1;
            }
        }
    }
}

// ---------------------------------------------------------------------------
// Split-K small GEMM (M=64): 64x64 tile, BK=32, 256 threads, 4x4/thread.
// grid = (nTiles, SPLITS, G). Writes raw partials; reduce_act finishes.
// ---------------------------------------------------------------------------
template<int SPLITS>
__global__ void gemm64s(const float* __restrict__ A,
                        const float* __restrict__ W,
                        float* __restrict__ part,
                        int Ntot, int K, int lda,
                        long aBS, long wBS)
{
    const int g     = blockIdx.z;
    const int split = blockIdx.y;
    A += (long)g * aBS;
    W += (long)g * wBS;

    __shared__ float As[64][33];
    __shared__ float Bs[64][33];

    const int tid = threadIdx.x;
    const int ty  = tid >> 4;
    const int tx  = tid & 15;
    const int n0  = blockIdx.x * 64;
    const int lr  = tid >> 5;
    const int lk  = tid & 31;

    const int stages   = K / 32;
    const int st_begin = (stages * split) / SPLITS;
    const int st_end   = (stages * (split + 1)) / SPLITS;
    const int nst      = st_end - st_begin;

    auto fetchA = [&](int st, float* r) {
        int k0 = st * 32;
#pragma unroll
        for (int i = 0; i < 8; i++)
            r[i] = A[(long)(i * 8 + lr) * lda + k0 + lk];
    };
    auto fetchB = [&](int st, float* r) {
        int k0 = st * 32;
#pragma unroll
        for (int i = 0; i < 8; i++) {
            int ng = n0 + i * 8 + lr; if (ng >= Ntot) ng = Ntot - 1;
            r[i] = W[(long)ng * K + k0 + lk];
        }
    };

    float rA[2][8], rB[2][8];
    fetchA(st_begin, rA[0]); fetchB(st_begin, rB[0]);
    if (nst > 1) { fetchA(st_begin + 1, rA[1]); fetchB(st_begin + 1, rB[1]); }

    float acc[4][4];
#pragma unroll
    for (int i = 0; i < 4; i++)
#pragma unroll
        for (int j = 0; j < 4; j++) acc[i][j] = 0.f;

    for (int s = 0; s < nst; s++) {
        float* cA = rA[s & 1];
        float* cB = rB[s & 1];
        __syncthreads();
#pragma unroll
        for (int i = 0; i < 8; i++) {
            As[i * 8 + lr][lk] = cA[i];
            Bs[i * 8 + lr][lk] = cB[i];
        }
        if (s + 2 < nst) { fetchA(st_begin + s + 2, cA); fetchB(st_begin + s + 2, cB); }
        __syncthreads();
#pragma unroll
        for (int kk = 0; kk < 32; kk++) {
            float a[4], b[4];
#pragma unroll
            for (int i = 0; i < 4; i++) a[i] = As[ty * 4 + i][kk];
#pragma unroll
            for (int j = 0; j < 4; j++) b[j] = Bs[tx * 4 + j][kk];
#pragma unroll
            for (int i = 0; i < 4; i++)
#pragma unroll
                for (int j = 0; j < 4; j++) acc[i][j] += a[i] * b[j];
        }
    }

    float* pbase = part + ((long)(g * SPLITS + split) * 64) * Ntot;
#pragma unroll
    for (int i = 0; i < 4; i++) {
        int m = ty * 4 + i;
#pragma unroll
        for (int j = 0; j < 4; j++) {
            int n = n0 + tx * 4 + j;
            if (n < Ntot) pbase[(long)m * Ntot + n] = acc[i][j];
        }
    }
}

// reduce split-K partials (ordered -> deterministic) + bias + activation
// MODE 1: tanh; MODE 3: identity
template<int MODE, int SPLITS>
__global__ void reduce_act(const float* __restrict__ part,
                           const float* __restrict__ bias,
                           float* __restrict__ C,
                           int Ntot, int ldc, long bBS, long cBS)
{
    const int g = blockIdx.y;
    int idx = blockIdx.x * blockDim.x + threadIdx.x;
    if (idx >= 64 * Ntot) return;
    int m = idx / Ntot, n = idx - m * Ntot;
    const float* pb = part + ((long)g * SPLITS * 64) * Ntot + (long)m * Ntot + n;
    float s = 0.f;
#pragma unroll
    for (int sp = 0; sp < SPLITS; sp++) s += pb[(long)sp * 64 * Ntot];
    float v = s + bias[(long)g * bBS + n];
    C[(long)g * cBS + (long)m * ldc + n] = (MODE == 1) ? tanhf(v) : v;
}

// hfus = vfus * qfus (elementwise)
__global__ void fuse_mul(const float* __restrict__ a, const float* __restrict__ b,
                         float* __restrict__ o, int n) {
    int i = blockIdx.x * blockDim.x + threadIdx.x;
    if (i < n) o[i] = a[i] * b[i];
}

// wgt[b,g,n] = sum_d xatt[b,n,d]*Watt[g,d] + batt[g]  (one warp per (b,n))
__global__ void wgt_kernel(const float* __restrict__ xatt,
                           const float* __restrict__ Watt,
                           const float* __restrict__ batt,
                           float* __restrict__ out)
{
    int w    = (blockIdx.x * blockDim.x + threadIdx.x) >> 5;
    int lane = threadIdx.x & 31;
    if (w >= MROWS) return;
    int b = w / WH_, n = w - b * WH_;
    const float* xr = xatt + (long)w * DA_;
    float s0 = 0.f, s1 = 0.f;
    for (int d = lane; d < DA_; d += 32) {
        float x = xr[d];
        s0 += x * Watt[d];
        s1 += x * Watt[DA_ + d];
    }
#pragma unroll
    for (int o = 16; o > 0; o >>= 1) {
        s0 += __shfl_down_sync(0xffffffffu, s0, o);
        s1 += __shfl_down_sync(0xffffffffu, s1, o);
    }
    if (lane == 0) {
        out[((long)b * G_ + 0) * WH_ + n] = s0 + batt[0];
        out[((long)b * G_ + 1) * WH_ + n] = s1 + batt[1];
    }
}

// softmax over 196 per (b,g)
__global__ void softmax196(const float* __restrict__ wgt, float* __restrict__ att)
{
    __shared__ float red[256];
    int bg = blockIdx.x;
    int t  = threadIdx.x;
    const float* in = wgt + (long)bg * WH_;
    float v = (t < WH_) ? in[t] : -1e30f;
    red[t] = v; __syncthreads();
    for (int s = 128; s > 0; s >>= 1) {
        if (t < s) red[t] = fmaxf(red[t], red[t + s]);
        __syncthreads();
    }
    float mx = red[0]; __syncthreads();
    float e = (t < WH_) ? expf(v - mx) : 0.f;
    red[t] = e; __syncthreads();
    for (int s = 128; s > 0; s >>= 1) {
        if (t < s) red[t] += red[t + s];
        __syncthreads();
    }
    float inv = 1.f / red[0];
    if (t < WH_) att[(long)bg * WH_ + t] = e * inv;
}

// v_att[b,g,d] = sum_n att[b,g,n] * input_v[b,d,n]
__global__ void vatt_kernel(const float* __restrict__ v,
                            const float* __restrict__ att,
                            float* __restrict__ vatt)
{
    __shared__ float a0[WH_], a1[WH_];
    int b = blockIdx.x;
    int t = threadIdx.x;
    if (t < WH_) {
        a0[t] = att[((long)b * G_ + 0) * WH_ + t];
        a1[t] = att[((long)b * G_ + 1) * WH_ + t];
    }
    __syncthreads();
    int lane = t & 31, dd = t >> 5;
    int d = blockIdx.y * 8 + dd;
    const float* row = v + ((long)b * DV_ + d) * WH_;
    float s0 = 0.f, s1 = 0.f;
    for (int n = lane; n < WH_; n += 32) {
        float x = row[n];
        s0 += x * a0[n];
        s1 += x * a1[n];
    }
#pragma unroll
    for (int o = 16; o > 0; o >>= 1) {
        s0 += __shfl_down_sync(0xffffffffu, s0, o);
        s1 += __shfl_down_sync(0xffffffffu, s1, o);
    }
    if (lane == 0) {
        vatt[((long)b * G_ + 0) * DV_ + d] = s0;
        vatt[((long)b * G_ + 1) * DV_ + d] = s1;
    }
}

// ---------------------------------------------------------------------------
extern "C" void kernel_launch(void* const* d_in, const int* in_sizes, int n_in,
                              void* d_out, int out_size)
{
    const float* input_q = (const float*)d_in[0];
    const float* input_v = (const float*)d_in[1];
    const float* Wv_att  = (const float*)d_in[2];
    const float* bv_att  = (const float*)d_in[3];
    const float* Wq_att  = (const float*)d_in[4];
    const float* bq_att  = (const float*)d_in[5];
    const float* Watt    = (const float*)d_in[6];
    const float* batt    = (const float*)d_in[7];
    const float* Wv_fus  = (const float*)d_in[8];
    const float* bv_fus  = (const float*)d_in[9];
    const float* Wq_fus  = (const float*)d_in[10];
    const float* bq_fus  = (const float*)d_in[11];
    const float* Wc      = (const float*)d_in[12];
    const float* bc      = (const float*)d_in[13];

    float* out     = (float*)d_out;
    float* wgt_out = out + B_ * NC_;

    float *xatt, *xq, *att, *vatt, *vfus, *qfus, *hfus, *partb;
    cudaGetSymbolAddress((void**)&xatt, g_xatt);
    cudaGetSymbolAddress((void**)&xq,   g_xq);
    cudaGetSymbolAddress((void**)&att,  g_att);
    cudaGetSymbolAddress((void**)&vatt, g_vatt);
    cudaGetSymbolAddress((void**)&vfus, g_vfus);
    cudaGetSymbolAddress((void**)&qfus, g_qfus);
    cudaGetSymbolAddress((void**)&hfus, g_hfus);
    cudaGetSymbolAddress((void**)&partb, g_part);

    cudaFuncSetAttribute(gemm1_mma, cudaFuncAttributeMaxDynamicSharedMemorySize, SMEM_G1);

    // 0) bf16 hi/lo prepack of GEMM1 operands
    pack_W<<<((size_t)DA_ * DV_ / 4 + 255) / 256, 256>>>(Wv_att);
    pack_A<<<dim3(7, DV_ / 32, B_), dim3(32, 8)>>>(input_v);

    // 1) xq = tanh(input_q @ Wq_att^T + bq_att)   [64, 1200]
    gemm64s<8><<<dim3(19, 8, 1), 256>>>(input_q, Wq_att, partb, DA_, DQ_, DQ_, 0, 0);
    reduce_act<1, 8><<<dim3((64 * DA_ + 255) / 256, 1), 256>>>(
        partb, bq_att, xq, DA_, DA_, 0, 0);

    // 2) xatt via mma.sync bf16 (3x split)        [12544, 1200]
    gemm1_mma<<<dim3((DA_ + 127) / 128, MROWS / 128), 256, SMEM_G1>>>(bv_att, xq, xatt);

    // 3) wgt (part of output)                     [64, 2, 196]
    wgt_kernel<<<(MROWS * 32 + 255) / 256, 256>>>(xatt, Watt, batt, wgt_out);

    // 4) att = softmax(wgt)
    softmax196<<<B_ * G_, 256>>>(wgt_out, att);

    // 5) v_att = att @ V                          [64, 2, 2048]
    vatt_kernel<<<dim3(B_, DV_ / 8), 256>>>(input_v, att, vatt);

    // 6) v_fus = tanh(v_att @ Wv_fus^T + b)       [64, 2400] (batched g)
    gemm64s<8><<<dim3(19, 8, G_), 256>>>(
        vatt, Wv_fus, partb, DH_, DV_, G_ * DV_, (long)DV_, (long)DH_ * DV_);
    reduce_act<1, 8><<<dim3((64 * DH_ + 255) / 256, G_), 256>>>(
        partb, bv_fus, vfus, DH_, G_ * DH_, (long)DH_, (long)DH_);

    // 7) q_fus = tanh(input_q @ Wq_fus^T + b)     [64, 2400]
    gemm64s<8><<<dim3(38, 8, 1), 256>>>(input_q, Wq_fus, partb, G_ * DH_, DQ_, DQ_, 0, 0);
    reduce_act<1, 8><<<dim3((64 * G_ * DH_ + 255) / 256, 1), 256>>>(
        partb, bq_fus, qfus, G_ * DH_, G_ * DH_, 0, 0);

    // 7b) hfus = vfus * qfus
    fuse_mul<<<(B_ * G_ * DH_ + 255) / 256, 256>>>(vfus, qfus, hfus, B_ * G_ * DH_);

    // 8) x = hfus @ Wc^T + bc                     [64, 3000]
    gemm64s<8><<<dim3(47, 8, 1), 256>>>(hfus, Wc, partb, NC_, G_ * DH_, G_ * DH_, 0, 0);
    reduce_act<3, 8><<<dim3((64 * NC_ + 255) / 256, 1), 256>>>(
        partb, bc, out, NC_, NC_, 0, 0);
}

// round 9
// speedup vs baseline: 4.1855x; 1.0079x over previous
#include <cuda_runtime.h>
#include <cuda_bf16.h>
#include <math.h>
#include <cstdint>

// Problem dims
#define B_   64
#define DV_  2048
#define WH_  196
#define DQ_  2400
#define DA_  1200
#define G_   2
#define DH_  1200
#define NC_  3000
#define MROWS (B_*WH_)   // 12544
#define NBLK_N 10        // DA_/128 column blocks in gemm1

// ---------------- scratch (device globals; no allocation allowed) ----------
__device__ float g_wgtp[NBLK_N * MROWS * G_];   // wgt partials, 1MB
__device__ float g_xq  [B_ * DA_];
__device__ float g_att [B_ * G_ * WH_];
__device__ float g_vatt[B_ * G_ * DV_];
__device__ float g_vfus[B_ * G_ * DH_];
__device__ float g_qfus[B_ * G_ * DH_];
__device__ float g_hfus[B_ * G_ * DH_];
__device__ float g_part[2 * 8 * 64 * NC_];      // split-K partials (max case)
// bf16 split operands for GEMM1 (A = V transposed to [M,K] K-major)
__device__ __nv_bfloat16 g_Ahi[(size_t)MROWS * DV_];
__device__ __nv_bfloat16 g_Alo[(size_t)MROWS * DV_];
__device__ __nv_bfloat16 g_Bhi[(size_t)DA_ * DV_];
__device__ __nv_bfloat16 g_Blo[(size_t)DA_ * DV_];

// ============================ PTX helpers ==================================
__device__ __forceinline__ uint32_t smem_u32(const void* p) {
    uint32_t a;
    asm("{ .reg .u64 t; cvta.to.shared.u64 t, %1; cvt.u32.u64 %0, t; }" : "=r"(a) : "l"(p));
    return a;
}
__device__ __forceinline__ void cp16(uint32_t dst, const void* src) {
    asm volatile("cp.async.cg.shared.global [%0], [%1], 16;" :: "r"(dst), "l"(src));
}
#define CP_COMMIT() asm volatile("cp.async.commit_group;" ::: "memory")
#define CP_WAIT(n)  asm volatile("cp.async.wait_group %0;" :: "n"(n) : "memory")

__device__ __forceinline__ void ldsm_x4(uint32_t* r, uint32_t addr) {
    asm volatile("ldmatrix.sync.aligned.m8n8.x4.shared.b16 {%0,%1,%2,%3}, [%4];"
                 : "=r"(r[0]), "=r"(r[1]), "=r"(r[2]), "=r"(r[3]) : "r"(addr));
}
__device__ __forceinline__ void mma_bf16(float* c, const uint32_t* a, const uint32_t* b) {
    asm volatile("mma.sync.aligned.m16n8k16.row.col.f32.bf16.bf16.f32 "
                 "{%0,%1,%2,%3}, {%4,%5,%6,%7}, {%8,%9}, {%0,%1,%2,%3};"
                 : "+f"(c[0]), "+f"(c[1]), "+f"(c[2]), "+f"(c[3])
                 : "r"(a[0]), "r"(a[1]), "r"(a[2]), "r"(a[3]), "r"(b[0]), "r"(b[1]));
}

// ============================ prepack kernels ==============================
__device__ __forceinline__ void split_bf16(float x, __nv_bfloat16& hi, __nv_bfloat16& lo) {
    hi = __float2bfloat16(x);
    lo = __float2bfloat16(x - __bfloat162float(hi));
}

__global__ void pack_W(const float* __restrict__ W) {
    size_t i = (size_t)blockIdx.x * blockDim.x + threadIdx.x;
    size_t total = (size_t)DA_ * DV_ / 4;
    if (i >= total) return;
    const float4 v = ((const float4*)W)[i];
    __nv_bfloat16 h0, l0, h1, l1, h2, l2, h3, l3;
    split_bf16(v.x, h0, l0); split_bf16(v.y, h1, l1);
    split_bf16(v.z, h2, l2); split_bf16(v.w, h3, l3);
    __nv_bfloat162* Hi = (__nv_bfloat162*)g_Bhi;
    __nv_bfloat162* Lo = (__nv_bfloat162*)g_Blo;
    Hi[i * 2 + 0] = __nv_bfloat162(h0, h1); Hi[i * 2 + 1] = __nv_bfloat162(h2, h3);
    Lo[i * 2 + 0] = __nv_bfloat162(l0, l1); Lo[i * 2 + 1] = __nv_bfloat162(l2, l3);
}

__global__ void pack_A(const float* __restrict__ V) {
    __shared__ float tile[32][33];
    int ns0 = blockIdx.x * 32;
    int k0  = blockIdx.y * 32;
    int b   = blockIdx.z;
    int tx = threadIdx.x, ty = threadIdx.y;   // (32, 8)
#pragma unroll
    for (int r = 0; r < 4; r++) {
        int kl = ty + r * 8;
        int ns = ns0 + tx;
        float v = (ns < WH_) ? V[((size_t)b * DV_ + (k0 + kl)) * WH_ + ns] : 0.f;
        tile[kl][tx] = v;
    }
    __syncthreads();
#pragma unroll
    for (int r = 0; r < 4; r++) {
        int nsl = ty + r * 8;
        int ns = ns0 + nsl;
        if (ns < WH_) {
            size_t m = (size_t)b * WH_ + ns;
            float v = tile[tx][nsl];
            __nv_bfloat16 hi, lo;
            split_bf16(v, hi, lo);
            g_Ahi[m * DV_ + k0 + tx] = hi;
            g_Alo[m * DV_ + k0 + tx] = lo;
        }
    }
}

// ============================ GEMM1 (mma.sync bf16, 3x split) ==============
// Computes xatt = tanh(tanh(A@W^T + bias)*xq) for a 128x128 tile and directly
// contracts it against Watt (G=2) -> wgt partials. xatt never hits DRAM.
#define APART  10240           // 128 * 80
#define STG_B  20480
#define STAGE  40960
#define NBUF   4
#define SMEM_G1 (NBUF * STAGE)  // 163840

__global__ void __launch_bounds__(256, 1)
gemm1_mma(const float* __restrict__ bias, const float* __restrict__ xq,
          const float* __restrict__ Watt, float* __restrict__ wgtp)
{
    extern __shared__ char sm[];
    const uint32_t sb = smem_u32(sm);
    const int tid = threadIdx.x, warp = tid >> 5, lane = tid & 31;
    const int m0 = blockIdx.y * 128;
    const int n0 = blockIdx.x * 128;
    const int wm = (warp & 1) * 64;
    const int wn = (warp >> 1) * 32;

    float acc[4][4][4];
#pragma unroll
    for (int mi = 0; mi < 4; mi++)
#pragma unroll
        for (int nf = 0; nf < 4; nf++)
#pragma unroll
            for (int e = 0; e < 4; e++) acc[mi][nf][e] = 0.f;

    const int r_a = tid >> 2, c_a = tid & 3;

    auto load_stage = [&](int ks, int buf) {
        const int k0 = ks * 32;
        const uint32_t dstA = sb + buf * STAGE;
        const uint32_t dstB = dstA + STG_B;
#pragma unroll
        for (int part = 0; part < 2; part++) {
            const __nv_bfloat16* src = part ? g_Alo : g_Ahi;
#pragma unroll
            for (int i = 0; i < 2; i++) {
                int row = r_a + i * 64;
                cp16(dstA + part * APART + row * 80 + c_a * 16,
                     src + (size_t)(m0 + row) * DV_ + k0 + c_a * 8);
            }
        }
#pragma unroll
        for (int part = 0; part < 2; part++) {
            const __nv_bfloat16* src = part ? g_Blo : g_Bhi;
#pragma unroll
            for (int i = 0; i < 2; i++) {
                int row = r_a + i * 64;
                int rg = n0 + row; if (rg >= DA_) rg = DA_ - 1;
                cp16(dstB + part * APART + row * 80 + c_a * 16,
                     src + (size_t)rg * DV_ + k0 + c_a * 8);
            }
        }
    };

    load_stage(0, 0); CP_COMMIT();
    load_stage(1, 1); CP_COMMIT();
    load_stage(2, 2); CP_COMMIT();

    const int NST = DV_ / 32;   // 64
    for (int ks = 0; ks < NST; ks++) {
        const int buf = ks % NBUF;
        const int rem = NST - 1 - ks;
        if (rem >= 2)      { CP_WAIT(2); }
        else if (rem == 1) { CP_WAIT(1); }
        else               { CP_WAIT(0); }
        __syncthreads();

        const uint32_t Ab = sb + buf * STAGE;
        const uint32_t Bb = Ab + STG_B;
#pragma unroll
        for (int kb2 = 0; kb2 < 2; kb2++) {
            const int kb = kb2 * 16;
            uint32_t a_hi[4][4], a_lo[4][4], b_hi[2][4], b_lo[2][4];
            const uint32_t aAddr = Ab + (wm + (lane & 15)) * 80 + kb * 2 + ((lane >> 4) << 4);
#pragma unroll
            for (int mi = 0; mi < 4; mi++) {
                ldsm_x4(a_hi[mi], aAddr + mi * 16 * 80);
                ldsm_x4(a_lo[mi], aAddr + APART + mi * 16 * 80);
            }
            const uint32_t bAddr = Bb + (wn + ((lane >> 4) << 3) + (lane & 7)) * 80
                                 + (kb + ((lane >> 3) & 1) * 8) * 2;
#pragma unroll
            for (int nj = 0; nj < 2; nj++) {
                ldsm_x4(b_hi[nj], bAddr + nj * 16 * 80);
                ldsm_x4(b_lo[nj], bAddr + APART + nj * 16 * 80);
            }
#pragma unroll
            for (int mi = 0; mi < 4; mi++)
#pragma unroll
                for (int nf = 0; nf < 4; nf++) {
                    const uint32_t* bh = &b_hi[nf >> 1][(nf & 1) * 2];
                    const uint32_t* bl = &b_lo[nf >> 1][(nf & 1) * 2];
                    mma_bf16(acc[mi][nf], a_hi[mi], bh);
                    mma_bf16(acc[mi][nf], a_hi[mi], bl);
                    mma_bf16(acc[mi][nf], a_lo[mi], bh);
                }
        }
        if (ks + 3 < NST) { load_stage(ks + 3, (ks + 3) % NBUF); CP_COMMIT(); }
    }

    // ---- epilogue: xatt = tanh(tanh(acc+bias)*xq); contract vs Watt ----
    // wpart smem overlay: [4 warpcol][128 rows][2 g]
    __syncthreads();      // all ldsm reads of stage buffers done before overlay
    float* wp = (float*)sm;
    const int wcol = warp >> 1;

#pragma unroll
    for (int mi = 0; mi < 4; mi++) {
        const int r0 = m0 + wm + mi * 16 + (lane >> 2);
        const int r1 = r0 + 8;
        const int b0 = r0 / WH_, b1 = r1 / WH_;
        const float* xq0 = xq + (size_t)b0 * DA_;
        const float* xq1 = xq + (size_t)b1 * DA_;
        float p00 = 0.f, p01 = 0.f, p10 = 0.f, p11 = 0.f;  // [row0/1][g0/1]
#pragma unroll
        for (int nf = 0; nf < 4; nf++) {
            const int n = n0 + wn + nf * 8 + (lane & 3) * 2;
            if (n < DA_) {
                const float bz0 = bias[n], bz1 = bias[n + 1];
                const float w00 = Watt[n],        w01 = Watt[n + 1];
                const float w10 = Watt[DA_ + n],  w11 = Watt[DA_ + n + 1];
                float x00 = tanhf(tanhf(acc[mi][nf][0] + bz0) * xq0[n]);
                float x01 = tanhf(tanhf(acc[mi][nf][1] + bz1) * xq0[n + 1]);
                float x10 = tanhf(tanhf(acc[mi][nf][2] + bz0) * xq1[n]);
                float x11 = tanhf(tanhf(acc[mi][nf][3] + bz1) * xq1[n + 1]);
                p00 += x00 * w00 + x01 * w01;
                p01 += x00 * w10 + x01 * w11;
                p10 += x10 * w00 + x11 * w01;
                p11 += x10 * w10 + x11 * w11;
            }
        }
        // reduce over the lane-quad (lane&3 spans n within the warp tile)
#pragma unroll
        for (int o = 1; o < 4; o <<= 1) {
            p00 += __shfl_xor_sync(0xffffffffu, p00, o);
            p01 += __shfl_xor_sync(0xffffffffu, p01, o);
            p10 += __shfl_xor_sync(0xffffffffu, p10, o);
            p11 += __shfl_xor_sync(0xffffffffu, p11, o);
        }
        if ((lane & 3) == 0) {
            int rl0 = wm + mi * 16 + (lane >> 2);
            wp[(wcol * 128 + rl0) * 2 + 0] = p00;
            wp[(wcol * 128 + rl0) * 2 + 1] = p01;
            wp[(wcol * 128 + rl0 + 8) * 2 + 0] = p10;
            wp[(wcol * 128 + rl0 + 8) * 2 + 1] = p11;
        }
    }
    __syncthreads();
    // cross-warp-column ordered sum: 128 rows x 2 g = 256 values
    {
        int row = tid >> 1, g = tid & 1;
        float s = wp[(0 * 128 + row) * 2 + g] + wp[(1 * 128 + row) * 2 + g]
                + wp[(2 * 128 + row) * 2 + g] + wp[(3 * 128 + row) * 2 + g];
        wgtp[((size_t)blockIdx.x * MROWS + m0 + row) * G_ + g] = s;
    }
}

// wgt_out[b,g,ns] = batt[g] + sum_nblk wgtp[nblk][m][g]   (ordered, deterministic)
__global__ void reduce_wgt(const float* __restrict__ wgtp,
                           const float* __restrict__ batt,
                           float* __restrict__ out)
{
    int idx = blockIdx.x * blockDim.x + threadIdx.x;   // m*2+g
    if (idx >= MROWS * G_) return;
    int m = idx >> 1, g = idx & 1;
    float s = 0.f;
#pragma unroll
    for (int nb = 0; nb < NBLK_N; nb++)
        s += wgtp[((size_t)nb * MROWS + m) * G_ + g];
    int b = m / WH_, ns = m - b * WH_;
    out[((size_t)b * G_ + g) * WH_ + ns] = s + batt[g];
}

// ---------------------------------------------------------------------------
// Split-K small GEMM (M=64): 64x64 tile, BK=32, 256 threads, 4x4/thread.
// ---------------------------------------------------------------------------
template<int SPLITS>
__global__ void gemm64s(const float* __restrict__ A,
                        const float* __restrict__ W,
                        float* __restrict__ part,
                        int Ntot, int K, int lda,
                        long aBS, long wBS)
{
    const int g     = blockIdx.z;
    const int split = blockIdx.y;
    A += (long)g * aBS;
    W += (long)g * wBS;

    __shared__ float As[64][33];
    __shared__ float Bs[64][33];

    const int tid = threadIdx.x;
    const int ty  = tid >> 4;
    const int tx  = tid & 15;
    const int n0  = blockIdx.x * 64;
    const int lr  = tid >> 5;
    const int lk  = tid & 31;

    const int stages   = K / 32;
    const int st_begin = (stages * split) / SPLITS;
    const int st_end   = (stages * (split + 1)) / SPLITS;
    const int nst      = st_end - st_begin;

    auto fetchA = [&](int st, float* r) {
        int k0 = st * 32;
#pragma unroll
        for (int i = 0; i < 8; i++)
            r[i] = A[(long)(i * 8 + lr) * lda + k0 + lk];
    };
    auto fetchB = [&](int st, float* r) {
        int k0 = st * 32;
#pragma unroll
        for (int i = 0; i < 8; i++) {
            int ng = n0 + i * 8 + lr; if (ng >= Ntot) ng = Ntot - 1;
            r[i] = W[(long)ng * K + k0 + lk];
        }
    };

    float rA[2][8], rB[2][8];
    fetchA(st_begin, rA[0]); fetchB(st_begin, rB[0]);
    if (nst > 1) { fetchA(st_begin + 1, rA[1]); fetchB(st_begin + 1, rB[1]); }

    float acc[4][4];
#pragma unroll
    for (int i = 0; i < 4; i++)
#pragma unroll
        for (int j = 0; j < 4; j++) acc[i][j] = 0.f;

    for (int s = 0; s < nst; s++) {
        float* cA = rA[s & 1];
        float* cB = rB[s & 1];
        __syncthreads();
#pragma unroll
        for (int i = 0; i < 8; i++) {
            As[i * 8 + lr][lk] = cA[i];
            Bs[i * 8 + lr][lk] = cB[i];
        }
        if (s + 2 < nst) { fetchA(st_begin + s + 2, cA); fetchB(st_begin + s + 2, cB); }
        __syncthreads();
#pragma unroll
        for (int kk = 0; kk < 32; kk++) {
            float a[4], b[4];
#pragma unroll
            for (int i = 0; i < 4; i++) a[i] = As[ty * 4 + i][kk];
#pragma unroll
            for (int j = 0; j < 4; j++) b[j] = Bs[tx * 4 + j][kk];
#pragma unroll
            for (int i = 0; i < 4; i++)
#pragma unroll
                for (int j = 0; j < 4; j++) acc[i][j] += a[i] * b[j];
        }
    }

    float* pbase = part + ((long)(g * SPLITS + split) * 64) * Ntot;
#pragma unroll
    for (int i = 0; i < 4; i++) {
        int m = ty * 4 + i;
#pragma unroll
        for (int j = 0; j < 4; j++) {
            int n = n0 + tx * 4 + j;
            if (n < Ntot) pbase[(long)m * Ntot + n] = acc[i][j];
        }
    }
}

// reduce split-K partials (ordered) + bias + activation. MODE 1: tanh; 3: id.
template<int MODE, int SPLITS>
__global__ void reduce_act(const float* __restrict__ part,
                           const float* __restrict__ bias,
                           float* __restrict__ C,
                           int Ntot, int ldc, long bBS, long cBS)
{
    const int g = blockIdx.y;
    int idx = blockIdx.x * blockDim.x + threadIdx.x;
    if (idx >= 64 * Ntot) return;
    int m = idx / Ntot, n = idx - m * Ntot;
    const float* pb = part + ((long)g * SPLITS * 64) * Ntot + (long)m * Ntot + n;
    float s = 0.f;
#pragma unroll
    for (int sp = 0; sp < SPLITS; sp++) s += pb[(long)sp * 64 * Ntot];
    float v = s + bias[(long)g * bBS + n];
    C[(long)g * cBS + (long)m * ldc + n] = (MODE == 1) ? tanhf(v) : v;
}

// hfus = vfus * qfus (elementwise)
__global__ void fuse_mul(const float* __restrict__ a, const float* __restrict__ b,
                         float* __restrict__ o, int n) {
    int i = blockIdx.x * blockDim.x + threadIdx.x;
    if (i < n) o[i] = a[i] * b[i];
}

// softmax over 196 per (b,g)
__global__ void softmax196(const float* __restrict__ wgt, float* __restrict__ att)
{
    __shared__ float red[256];
    int bg = blockIdx.x;
    int t  = threadIdx.x;
    const float* in = wgt + (long)bg * WH_;
    float v = (t < WH_) ? in[t] : -1e30f;
    red[t] = v; __syncthreads();
    for (int s = 128; s > 0; s >>= 1) {
        if (t < s) red[t] = fmaxf(red[t], red[t + s]);
        __syncthreads();
    }
    float mx = red[0]; __syncthreads();
    float e = (t < WH_) ? expf(v - mx) : 0.f;
    red[t] = e; __syncthreads();
    for (int s = 128; s > 0; s >>= 1) {
        if (t < s) red[t] += red[t + s];
        __syncthreads();
    }
    float inv = 1.f / red[0];
    if (t < WH_) att[(long)bg * WH_ + t] = e * inv;
}

// v_att[b,g,d] = sum_n att[b,g,n] * input_v[b,d,n]
__global__ void vatt_kernel(const float* __restrict__ v,
                            const float* __restrict__ att,
                            float* __restrict__ vatt)
{
    __shared__ float a0[WH_], a1[WH_];
    int b = blockIdx.x;
    int t = threadIdx.x;
    if (t < WH_) {
        a0[t] = att[((long)b * G_ + 0) * WH_ + t];
        a1[t] = att[((long)b * G_ + 1) * WH_ + t];
    }
    __syncthreads();
    int lane = t & 31, dd = t >> 5;
    int d = blockIdx.y * 8 + dd;
    const float* row = v + ((long)b * DV_ + d) * WH_;
    float s0 = 0.f, s1 = 0.f;
    for (int n = lane; n < WH_; n += 32) {
        float x = row[n];
        s0 += x * a0[n];
        s1 += x * a1[n];
    }
#pragma unroll
    for (int o = 16; o > 0; o >>= 1) {
        s0 += __shfl_down_sync(0xffffffffu, s0, o);
        s1 += __shfl_down_sync(0xffffffffu, s1, o);
    }
    if (lane == 0) {
        vatt[((long)b * G_ + 0) * DV_ + d] = s0;
        vatt[((long)b * G_ + 1) * DV_ + d] = s1;
    }
}

// ---------------------------------------------------------------------------
extern "C" void kernel_launch(void* const* d_in, const int* in_sizes, int n_in,
                              void* d_out, int out_size)
{
    const float* input_q = (const float*)d_in[0];
    const float* input_v = (const float*)d_in[1];
    const float* Wv_att  = (const float*)d_in[2];
    const float* bv_att  = (const float*)d_in[3];
    const float* Wq_att  = (const float*)d_in[4];
    const float* bq_att  = (const float*)d_in[5];
    const float* Watt    = (const float*)d_in[6];
    const float* batt    = (const float*)d_in[7];
    const float* Wv_fus  = (const float*)d_in[8];
    const float* bv_fus  = (const float*)d_in[9];
    const float* Wq_fus  = (const float*)d_in[10];
    const float* bq_fus  = (const float*)d_in[11];
    const float* Wc      = (const float*)d_in[12];
    const float* bc      = (const float*)d_in[13];

    float* out     = (float*)d_out;
    float* wgt_out = out + B_ * NC_;

    float *wgtp, *xq, *att, *vatt, *vfus, *qfus, *hfus, *partb;
    cudaGetSymbolAddress((void**)&wgtp, g_wgtp);
    cudaGetSymbolAddress((void**)&xq,   g_xq);
    cudaGetSymbolAddress((void**)&att,  g_att);
    cudaGetSymbolAddress((void**)&vatt, g_vatt);
    cudaGetSymbolAddress((void**)&vfus, g_vfus);
    cudaGetSymbolAddress((void**)&qfus, g_qfus);
    cudaGetSymbolAddress((void**)&hfus, g_hfus);
    cudaGetSymbolAddress((void**)&partb, g_part);

    cudaFuncSetAttribute(gemm1_mma, cudaFuncAttributeMaxDynamicSharedMemorySize, SMEM_G1);

    // 0) bf16 hi/lo prepack of GEMM1 operands
    pack_W<<<((size_t)DA_ * DV_ / 4 + 255) / 256, 256>>>(Wv_att);
    pack_A<<<dim3(7, DV_ / 32, B_), dim3(32, 8)>>>(input_v);

    // 1) xq = tanh(input_q @ Wq_att^T + bq_att)   [64, 1200]
    gemm64s<8><<<dim3(19, 8, 1), 256>>>(input_q, Wq_att, partb, DA_, DQ_, DQ_, 0, 0);
    reduce_act<1, 8><<<dim3((64 * DA_ + 255) / 256, 1), 256>>>(
        partb, bq_att, xq, DA_, DA_, 0, 0);

    // 2) fused gemm1 + wgt contraction (xatt never materialized)
    gemm1_mma<<<dim3(NBLK_N, MROWS / 128), 256, SMEM_G1>>>(bv_att, xq, Watt, wgtp);

    // 3) wgt (part of output)
    reduce_wgt<<<(MROWS * G_ + 255) / 256, 256>>>(wgtp, batt, wgt_out);

    // 4) att = softmax(wgt)
    softmax196<<<B_ * G_, 256>>>(wgt_out, att);

    // 5) v_att = att @ V                          [64, 2, 2048]
    vatt_kernel<<<dim3(B_, DV_ / 8), 256>>>(input_v, att, vatt);

    // 6) v_fus = tanh(v_att @ Wv_fus^T + b)       [64, 2400] (batched g)
    gemm64s<8><<<dim3(19, 8, G_), 256>>>(
        vatt, Wv_fus, partb, DH_, DV_, G_ * DV_, (long)DV_, (long)DH_ * DV_);
    reduce_act<1, 8><<<dim3((64 * DH_ + 255) / 256, G_), 256>>>(
        partb, bv_fus, vfus, DH_, G_ * DH_, (long)DH_, (long)DH_);

    // 7) q_fus = tanh(input_q @ Wq_fus^T + b)     [64, 2400]
    gemm64s<8><<<dim3(38, 8, 1), 256>>>(input_q, Wq_fus, partb, G_ * DH_, DQ_, DQ_, 0, 0);
    reduce_act<1, 8><<<dim3((64 * G_ * DH_ + 255) / 256, 1), 256>>>(
        partb, bq_fus, qfus, G_ * DH_, G_ * DH_, 0, 0);

    // 7b) hfus = vfus * qfus
    fuse_mul<<<(B_ * G_ * DH_ + 255) / 256, 256>>>(vfus, qfus, hfus, B_ * G_ * DH_);

    // 8) x = hfus @ Wc^T + bc                     [64, 3000]
    gemm64s<8><<<dim3(47, 8, 1), 256>>>(hfus, Wc, partb, NC_, G_ * DH_, G_ * DH_, 0, 0);
    reduce_act<3, 8><<<dim3((64 * NC_ + 255) / 256, 1), 256>>>(
        partb, bc, out, NC_, NC_, 0, 0);
}